// round 1
// baseline (speedup 1.0000x reference)
#include <cuda_runtime.h>
#include <math.h>

#define S_    1024
#define H_    32
#define KSEL  8
#define D_    128
#define E_    1024
#define NE    (S_*KSEL)       // 8192
#define SCALE_ 0.08838834764831845f   // 128^-0.5
#define MAXPOS 8191

// ---------------- scratch (static device globals; no allocation) ----------------
__device__ float g_q[NE*D_];
__device__ float g_k[NE*D_];
__device__ float g_v[NE*D_];
__device__ float g_mid[S_*E_];
__device__ int   g_head_idx[NE];
__device__ float g_head_w[NE];
__device__ float g_probs[S_*H_];
__device__ float g_ent[S_];
__device__ float g_z[S_];
__device__ int   g_primary[S_];
__device__ int   g_nh[H_];
__device__ int   g_off[H_+1];
__device__ int   g_perm[NE];
__device__ int   g_hd[NE];
__device__ int   g_pos[NE];
__device__ float g_cos[NE*64];
__device__ float g_sin[NE*64];
__device__ int   g_tile_head[300];
__device__ int   g_tile_start[300];
__device__ int   g_tile_m[300];
__device__ int   g_ntiles;

// ---------------- K1: router — logits, softmax stats, top-8, head weights ------
__global__ void k_router(const float* __restrict__ x, const float* __restrict__ Wr) {
    __shared__ float xs[E_];
    __shared__ float part[8][H_];
    int s = blockIdx.x, t = threadIdx.x;
    for (int i = t; i < E_; i += 256) xs[i] = x[s*E_ + i];
    __syncthreads();
    int c = t & 31, pr = t >> 5;
    float acc = 0.f;
    int e0 = pr * 128;
    #pragma unroll 4
    for (int e = e0; e < e0 + 128; e++) acc += xs[e] * Wr[e*H_ + c];
    part[pr][c] = acc;
    __syncthreads();
    if (t < 32) {
        float l = 0.f;
        #pragma unroll
        for (int p = 0; p < 8; p++) l += part[p][t];
        // warp softmax over H=32
        float m = l;
        for (int o = 16; o; o >>= 1) m = fmaxf(m, __shfl_xor_sync(0xffffffffu, m, o));
        float ex = expf(l - m);
        float sum = ex;
        for (int o = 16; o; o >>= 1) sum += __shfl_xor_sync(0xffffffffu, sum, o);
        float p = ex / sum;
        g_probs[s*H_ + t] = p;
        float et = p * logf(p + 1e-8f);
        float ent = et;
        for (int o = 16; o; o >>= 1) ent += __shfl_xor_sync(0xffffffffu, ent, o);
        if (t == 0) {
            g_ent[s] = -ent;                       // positive entropy
            float lse = m + logf(sum);
            g_z[s] = lse * lse;
        }
        // top-8 (descending, lower index wins ties — matches jax.lax.top_k)
        float lv = l;
        float topl[KSEL];
        int   topi[KSEL];
        for (int kk = 0; kk < KSEL; kk++) {
            float v = lv; int idx = t;
            for (int o = 16; o; o >>= 1) {
                float ov = __shfl_xor_sync(0xffffffffu, v, o);
                int   oi = __shfl_xor_sync(0xffffffffu, idx, o);
                if (ov > v || (ov == v && oi < idx)) { v = ov; idx = oi; }
            }
            if (t == 0) { topl[kk] = v; topi[kk] = idx; }
            if (t == idx) lv = -INFINITY;
        }
        if (t == 0) {
            for (int kk = 0; kk < KSEL; kk++) g_head_idx[s*KSEL + kk] = topi[kk];
            g_primary[s] = topi[0];
            float m2 = topl[0], sm2 = 0.f, w[KSEL];
            for (int kk = 0; kk < KSEL; kk++) { w[kk] = expf(topl[kk] - m2); sm2 += w[kk]; }
            float inv2 = 1.f / sm2;
            for (int kk = 0; kk < KSEL; kk++) g_head_w[s*KSEL + kk] = w[kk] * inv2;
        }
    }
}

// ---------------- K2: group-by-head build (deterministic, no atomics) ----------
__global__ void k_build(const int* __restrict__ head_counts) {
    // 256 threads: (head h = t&31, chunk ch = t>>5), 8 chunks of 1024 entries
    __shared__ int ccnt[8][H_];
    int t = threadIdx.x;
    int h = t & 31, ch = t >> 5;
    int c0 = ch * 1024, c1 = c0 + 1024;
    int cnt = 0;
    for (int i = c0; i < c1; i++) cnt += (g_head_idx[i] == h);
    ccnt[ch][h] = cnt;
    __syncthreads();
    if (t < 32) {
        int tot = 0;
        #pragma unroll
        for (int c = 0; c < 8; c++) tot += ccnt[c][t];
        g_nh[t] = tot;
    }
    __syncthreads();
    if (t == 0) {
        int o = 0;
        for (int hh = 0; hh < H_; hh++) { g_off[hh] = o; o += g_nh[hh]; }
        g_off[H_] = o;
        int nt = 0;
        for (int hh = 0; hh < H_; hh++) {
            for (int st = 0; st < g_nh[hh]; st += 32) {
                g_tile_head[nt] = hh;
                g_tile_start[nt] = g_off[hh] + st;
                g_tile_m[nt] = min(32, g_nh[hh] - st);
                nt++;
            }
        }
        g_ntiles = nt;
    }
    __syncthreads();
    int base = g_off[h];
    for (int c = 0; c < ch; c++) base += ccnt[c][h];
    int hc = head_counts[h];
    int local = 0;
    for (int i = c0; i < c1; i++) {
        if (g_head_idx[i] == h) {
            int pp = base + local;
            g_perm[pp] = i;
            g_hd[pp] = h;
            int rank = pp - g_off[h];
            int pos = rank + hc;
            pos = max(0, min(pos, MAXPOS));
            g_pos[pp] = pos;
            local++;
        }
    }
}

// ---------------- K2b: RoPE cos/sin table (double angle, reduced) --------------
__global__ void k_ropetab() {
    int j = blockIdx.x;
    int i = threadIdx.x;             // 0..63
    int pos = g_pos[j];
    double ex  = (double)(2 * i) / 128.0;
    double inv = pow(10000.0, -ex);
    double ang = (double)pos * inv;
    const double TWO_PI = 6.283185307179586476925286766559;
    double r = ang - floor(ang / TWO_PI + 0.5) * TWO_PI;   // |r| <= pi
    float fr = (float)r;
    g_cos[j*64 + i] = cosf(fr);
    g_sin[j*64 + i] = sinf(fr);
}

// ---------------- K3: grouped QKV GEMM + RoPE ----------------------------------
// tile: 32 tokens x 128 outputs, Kdim chunked by 64; all three W matrices share Xs.
__global__ void k_qkv(const float* __restrict__ x,
                      const float* __restrict__ Wq,
                      const float* __restrict__ Wk,
                      const float* __restrict__ Wv) {
    int tb = blockIdx.x;
    if (tb >= g_ntiles) return;
    __shared__ float Xs[64][32];       // [k][row]
    __shared__ float Ws[64][128];      // [k][col]; reused as Sbuf[32][128] in epilogue
    __shared__ int srow[32];
    int t = threadIdx.x;
    int h     = g_tile_head[tb];
    int start = g_tile_start[tb];
    int m     = g_tile_m[tb];
    if (t < 32) {
        int j = start + ((t < m) ? t : 0);
        srow[t] = g_perm[j] >> 3;      // token index (entry = s*8+kk)
    }
    __syncthreads();

    int tx = t & 31, ty = t >> 5;      // cols tx*4..+3, rows ty*4..+3
    float acc[3][4][4];
    #pragma unroll
    for (int w = 0; w < 3; w++)
        #pragma unroll
        for (int i = 0; i < 4; i++)
            #pragma unroll
            for (int jj = 0; jj < 4; jj++) acc[w][i][jj] = 0.f;

    const float* Wm0 = Wq; const float* Wm1 = Wk; const float* Wm2 = Wv;

    for (int kc = 0; kc < E_; kc += 64) {
        __syncthreads();
        { // load Xs transposed: Xs[k][i] = x[srow[i]][kc+k]
            int i = t & 31, kb = t >> 5;
            int sr = srow[i];
            #pragma unroll
            for (int k2 = kb; k2 < 64; k2 += 8)
                Xs[k2][i] = x[sr*E_ + kc + k2];
        }
        #pragma unroll
        for (int w = 0; w < 3; w++) {
            __syncthreads();
            const float* W = (w == 0) ? Wm0 : (w == 1) ? Wm1 : Wm2;
            // Ws[r][c] = W[(kc+r)*4096 + h*128 + c], vectorized
            for (int idx = t; idx < 64*32; idx += 256) {
                int r = idx >> 5, c4 = idx & 31;
                float4 v = *(const float4*)&W[(size_t)(kc + r)*(H_*D_) + h*D_ + c4*4];
                *(float4*)&Ws[r][c4*4] = v;
            }
            __syncthreads();
            #pragma unroll 8
            for (int k2 = 0; k2 < 64; k2++) {
                float4 xv = *(const float4*)&Xs[k2][ty*4];
                float4 wv = *(const float4*)&Ws[k2][tx*4];
                float rx[4] = {xv.x, xv.y, xv.z, xv.w};
                float rw[4] = {wv.x, wv.y, wv.z, wv.w};
                #pragma unroll
                for (int i = 0; i < 4; i++)
                    #pragma unroll
                    for (int jj = 0; jj < 4; jj++)
                        acc[w][i][jj] += rx[i] * rw[jj];
            }
        }
    }

    // epilogue: stage per-matrix tile into smem, apply rope (q,k), store
    float (*Sb)[128] = (float (*)[128])Ws;
    #pragma unroll
    for (int w = 0; w < 3; w++) {
        __syncthreads();
        #pragma unroll
        for (int i = 0; i < 4; i++)
            #pragma unroll
            for (int jj = 0; jj < 4; jj++)
                Sb[ty*4 + i][tx*4 + jj] = acc[w][i][jj];
        __syncthreads();
        float* dst = (w == 0) ? g_q : (w == 1) ? g_k : g_v;
        for (int idx = t; idx < 32*128; idx += 256) {
            int r = idx >> 7, c = idx & 127;
            if (r < m) {
                int j = start + r;
                float val = Sb[r][c];
                float outv;
                if (w < 2) {
                    int ih = (c < 64) ? c : (c - 64);
                    float cs = g_cos[j*64 + ih], sn = g_sin[j*64 + ih];
                    if (c < 64) outv = val * cs - Sb[r][c + 64] * sn;
                    else        outv = val * cs + Sb[r][c - 64] * sn;
                } else outv = val;
                dst[(size_t)j*D_ + c] = outv;
            }
        }
    }
}

// ---------------- K4: per-head causal attention, block per query ----------------
__global__ void k_attn() {
    extern __shared__ float sm[];
    float* sq  = sm;          // 128
    float* red = sm + 128;    // 128
    float* sc  = sm + 256;    // up to 8192 scores
    int j = blockIdx.x, t = threadIdx.x;     // 128 threads
    int h   = g_hd[j];
    int off = g_off[h];
    int nk  = j - off + 1;
    sq[t] = g_q[(size_t)j*D_ + t];
    __syncthreads();
    // scores
    const float4* qr = (const float4*)sq;
    for (int kk = t; kk < nk; kk += 128) {
        const float4* kr = (const float4*)(g_k + (size_t)(off + kk)*D_);
        float d = 0.f;
        #pragma unroll
        for (int c = 0; c < 32; c++) {
            float4 kv = kr[c], qv = qr[c];
            d += qv.x*kv.x + qv.y*kv.y + qv.z*kv.z + qv.w*kv.w;
        }
        sc[kk] = d * SCALE_;
    }
    __syncthreads();
    // max
    float mx = -1e30f;
    for (int kk = t; kk < nk; kk += 128) mx = fmaxf(mx, sc[kk]);
    red[t] = mx; __syncthreads();
    for (int s2 = 64; s2; s2 >>= 1) { if (t < s2) red[t] = fmaxf(red[t], red[t + s2]); __syncthreads(); }
    mx = red[0];
    __syncthreads();
    // exp + sum
    float sume = 0.f;
    for (int kk = t; kk < nk; kk += 128) { float e2 = expf(sc[kk] - mx); sc[kk] = e2; sume += e2; }
    red[t] = sume; __syncthreads();
    for (int s2 = 64; s2; s2 >>= 1) { if (t < s2) red[t] += red[t + s2]; __syncthreads(); }
    float inv = 1.f / red[0];
    // PV: thread t owns output dim t (coalesced v reads)
    float acc = 0.f;
    for (int kk = 0; kk < nk; kk++)
        acc += sc[kk] * g_v[(size_t)(off + kk)*D_ + t];
    int e = g_perm[j];
    g_mid[(size_t)e*D_ + t] = acc * inv * g_head_w[e];
}

// ---------------- K5: output projection mid[1024x1024] @ Wo[1024x1024] ----------
__global__ void k_outproj(const float* __restrict__ Wo, float* __restrict__ out) {
    __shared__ float As[16][68];   // [k][row], padded stride 68 (16B-aligned float4)
    __shared__ float Bs[16][64];   // [k][col]
    int bx = blockIdx.x, by = blockIdx.y;
    int t = threadIdx.x;
    int tx = t & 15, ty = t >> 4;
    float acc[4][4];
    #pragma unroll
    for (int i = 0; i < 4; i++)
        #pragma unroll
        for (int jj = 0; jj < 4; jj++) acc[i][jj] = 0.f;

    for (int kc = 0; kc < 1024; kc += 16) {
        __syncthreads();
        for (int idx = t; idx < 64*16; idx += 256) {
            int r = idx >> 4, k2 = idx & 15;
            As[k2][r] = g_mid[(size_t)(by*64 + r)*1024 + kc + k2];
        }
        for (int idx = t; idx < 16*64; idx += 256) {
            int k2 = idx >> 6, c = idx & 63;
            Bs[k2][c] = Wo[(size_t)(kc + k2)*1024 + bx*64 + c];
        }
        __syncthreads();
        #pragma unroll
        for (int k2 = 0; k2 < 16; k2++) {
            float4 av = *(const float4*)&As[k2][ty*4];
            float4 bv = *(const float4*)&Bs[k2][tx*4];
            float ra[4] = {av.x, av.y, av.z, av.w};
            float rb[4] = {bv.x, bv.y, bv.z, bv.w};
            #pragma unroll
            for (int i = 0; i < 4; i++)
                #pragma unroll
                for (int jj = 0; jj < 4; jj++)
                    acc[i][jj] += ra[i] * rb[jj];
        }
    }
    #pragma unroll
    for (int i = 0; i < 4; i++)
        #pragma unroll
        for (int jj = 0; jj < 4; jj++)
            out[(size_t)(by*64 + ty*4 + i)*1024 + bx*64 + tx*4 + jj] = acc[i][jj];
}

// ---------------- K6: counts + aux loss (deterministic reductions) --------------
__global__ void k_final(const int* __restrict__ head_counts, float* __restrict__ out, int out_size) {
    __shared__ float fb[H_];
    int t = threadIdx.x;   // 32 threads
    float psum = 0.f; int fcnt = 0;
    for (int s = 0; s < S_; s++) {
        psum += g_probs[s*H_ + t];
        fcnt += (g_primary[s] == t);
    }
    float f = (float)fcnt / (float)S_;
    float p = psum / (float)S_;
    fb[t] = f * p;
    if (out_size >= S_*E_ + H_)
        out[S_*E_ + t] = (float)(g_nh[t] + head_counts[t]);
    float es = 0.f, zs = 0.f;
    for (int s = t; s < S_; s += 32) { es += g_ent[s]; zs += g_z[s]; }
    for (int o = 16; o; o >>= 1) {
        es += __shfl_xor_sync(0xffffffffu, es, o);
        zs += __shfl_xor_sync(0xffffffffu, zs, o);
    }
    __syncwarp();
    if (t == 0) {
        float bal = 0.f;
        for (int hh = 0; hh < H_; hh++) bal += fb[hh];
        bal *= (float)H_;
        float ent_loss = -es / (float)S_;
        float z_loss   = (zs / (float)S_) * 0.01f;
        float aux = 0.01f * bal + 0.01f * ent_loss + z_loss;
        if (out_size >= S_*E_ + H_ + 1) out[S_*E_ + H_] = aux;
    }
}

// ---------------- launch ---------------------------------------------------------
extern "C" void kernel_launch(void* const* d_in, const int* in_sizes, int n_in,
                              void* d_out, int out_size) {
    const float* x  = (const float*)d_in[0];
    const float* Wq = (const float*)d_in[1];
    const float* Wk = (const float*)d_in[2];
    const float* Wv = (const float*)d_in[3];
    const float* Wr = (const float*)d_in[4];
    const float* Wo = (const float*)d_in[5];
    const int*   hc = (const int*)d_in[6];
    float* out = (float*)d_out;

    k_router<<<S_, 256>>>(x, Wr);
    k_build<<<1, 256>>>(hc);
    k_ropetab<<<NE, 64>>>();
    k_qkv<<<288, 256>>>(x, Wq, Wk, Wv);
    k_attn<<<NE, 128, (256 + NE) * sizeof(float)>>>();
    k_outproj<<<dim3(16, 16), 256>>>(Wo, out);
    k_final<<<1, 32>>>(hc, out, out_size);
}

// round 2
// speedup vs baseline: 1.3388x; 1.3388x over previous
#include <cuda_runtime.h>
#include <cuda_bf16.h>
#include <math.h>

#define S_    1024
#define H_    32
#define KSEL  8
#define D_    128
#define E_    1024
#define NE    (S_*KSEL)       // 8192
#define SCALE_ 0.08838834764831845f   // 128^-0.5
#define MAXPOS 8191

// ---------------- scratch (static device globals; no allocation) ----------------
__device__ float g_q[NE*D_];
__device__ float g_k[NE*D_];
__device__ float g_v[NE*D_];
__device__ float g_mid[S_*E_];
__device__ int   g_head_idx[NE];
__device__ float g_head_w[NE];
__device__ float g_probs[S_*H_];
__device__ float g_ent[S_];
__device__ float g_z[S_];
__device__ int   g_primary[S_];
__device__ int   g_nh[H_];
__device__ int   g_off[H_+1];
__device__ int   g_perm[NE];
__device__ int   g_hd[NE];
__device__ int   g_pos[NE];
__device__ float g_cos[NE*64];
__device__ float g_sin[NE*64];
__device__ int   g_tile_head[300];
__device__ int   g_tile_start[300];
__device__ int   g_tile_m[300];
__device__ int   g_ntiles;
__device__ int   g_t64_head[176];
__device__ int   g_t64_start[176];
__device__ int   g_t64_m[176];
__device__ int   g_ntiles64;

// split-bf16 weights (hi/lo). Layouts match the source fp32 matrices.
__device__ unsigned short g_wh[3u*1024u*4096u];   // Wq,Wk,Wv hi
__device__ unsigned short g_wl[3u*1024u*4096u];   // lo
__device__ unsigned short g_woh[1024u*1024u];     // Wo hi
__device__ unsigned short g_wol[1024u*1024u];     // lo

// ---------------- mma helpers ---------------------------------------------------
__device__ __forceinline__ void ldm4(unsigned r[4], unsigned a) {
    asm volatile("ldmatrix.sync.aligned.m8n8.x4.shared.b16 {%0,%1,%2,%3},[%4];"
        : "=r"(r[0]), "=r"(r[1]), "=r"(r[2]), "=r"(r[3]) : "r"(a));
}
__device__ __forceinline__ void ldm4t(unsigned r[4], unsigned a) {
    asm volatile("ldmatrix.sync.aligned.m8n8.x4.trans.shared.b16 {%0,%1,%2,%3},[%4];"
        : "=r"(r[0]), "=r"(r[1]), "=r"(r[2]), "=r"(r[3]) : "r"(a));
}
__device__ __forceinline__ void mma16816(float d[4], const unsigned a[4], const unsigned b[2]) {
    asm volatile("mma.sync.aligned.m16n8k16.row.col.f32.bf16.bf16.f32 "
        "{%0,%1,%2,%3},{%4,%5,%6,%7},{%8,%9},{%0,%1,%2,%3};"
        : "+f"(d[0]), "+f"(d[1]), "+f"(d[2]), "+f"(d[3])
        : "r"(a[0]), "r"(a[1]), "r"(a[2]), "r"(a[3]), "r"(b[0]), "r"(b[1]));
}
__device__ __forceinline__ void split8(const float* f, uint4& h, uint4& l) {
    unsigned hu[4], lu[4];
    #pragma unroll
    for (int i = 0; i < 4; i++) {
        float a = f[2*i], b = f[2*i+1];
        __nv_bfloat16 ha = __float2bfloat16(a), hb = __float2bfloat16(b);
        float ra = a - __bfloat162float(ha), rb = b - __bfloat162float(hb);
        __nv_bfloat16 la = __float2bfloat16(ra), lb = __float2bfloat16(rb);
        hu[i] = (unsigned)__bfloat16_as_ushort(ha) | ((unsigned)__bfloat16_as_ushort(hb) << 16);
        lu[i] = (unsigned)__bfloat16_as_ushort(la) | ((unsigned)__bfloat16_as_ushort(lb) << 16);
    }
    h = make_uint4(hu[0], hu[1], hu[2], hu[3]);
    l = make_uint4(lu[0], lu[1], lu[2], lu[3]);
}

// ---------------- K0: split weights into bf16 hi/lo ------------------------------
__global__ void k_split(const float* __restrict__ Wq, const float* __restrict__ Wk,
                        const float* __restrict__ Wv, const float* __restrict__ Wo) {
    const unsigned WQKV4 = 3u*1024u*4096u/4u;   // 3,145,728 float4 groups
    unsigned i4 = blockIdx.x*256u + threadIdx.x;
    const float* src;
    unsigned e4;
    unsigned short *dh, *dl;
    unsigned di;
    if (i4 < WQKV4) {
        unsigned w = i4 / 1048576u;
        e4 = i4 % 1048576u;
        src = (w == 0) ? Wq : (w == 1) ? Wk : Wv;
        dh = g_wh; dl = g_wl; di = i4;
    } else {
        e4 = i4 - WQKV4;
        src = Wo;
        dh = g_woh; dl = g_wol; di = e4;
    }
    float4 v = ((const float4*)src)[e4];
    float f[4] = {v.x, v.y, v.z, v.w};
    unsigned hu[2], lu[2];
    #pragma unroll
    for (int i = 0; i < 2; i++) {
        float a = f[2*i], b = f[2*i+1];
        __nv_bfloat16 ha = __float2bfloat16(a), hb = __float2bfloat16(b);
        float ra = a - __bfloat162float(ha), rb = b - __bfloat162float(hb);
        __nv_bfloat16 la = __float2bfloat16(ra), lb = __float2bfloat16(rb);
        hu[i] = (unsigned)__bfloat16_as_ushort(ha) | ((unsigned)__bfloat16_as_ushort(hb) << 16);
        lu[i] = (unsigned)__bfloat16_as_ushort(la) | ((unsigned)__bfloat16_as_ushort(lb) << 16);
    }
    ((uint2*)dh)[di] = make_uint2(hu[0], hu[1]);
    ((uint2*)dl)[di] = make_uint2(lu[0], lu[1]);
}

// ---------------- K1: router — logits, softmax stats, top-8, head weights ------
__global__ void k_router(const float* __restrict__ x, const float* __restrict__ Wr) {
    __shared__ float xs[E_];
    __shared__ float part[8][H_];
    int s = blockIdx.x, t = threadIdx.x;
    for (int i = t; i < E_; i += 256) xs[i] = x[s*E_ + i];
    __syncthreads();
    int c = t & 31, pr = t >> 5;
    float acc = 0.f;
    int e0 = pr * 128;
    #pragma unroll 4
    for (int e = e0; e < e0 + 128; e++) acc += xs[e] * Wr[e*H_ + c];
    part[pr][c] = acc;
    __syncthreads();
    if (t < 32) {
        float l = 0.f;
        #pragma unroll
        for (int p = 0; p < 8; p++) l += part[p][t];
        float m = l;
        for (int o = 16; o; o >>= 1) m = fmaxf(m, __shfl_xor_sync(0xffffffffu, m, o));
        float ex = expf(l - m);
        float sum = ex;
        for (int o = 16; o; o >>= 1) sum += __shfl_xor_sync(0xffffffffu, sum, o);
        float p = ex / sum;
        g_probs[s*H_ + t] = p;
        float et = p * logf(p + 1e-8f);
        float ent = et;
        for (int o = 16; o; o >>= 1) ent += __shfl_xor_sync(0xffffffffu, ent, o);
        if (t == 0) {
            g_ent[s] = -ent;
            float lse = m + logf(sum);
            g_z[s] = lse * lse;
        }
        float lv = l;
        float topl[KSEL];
        int   topi[KSEL];
        for (int kk = 0; kk < KSEL; kk++) {
            float v = lv; int idx = t;
            for (int o = 16; o; o >>= 1) {
                float ov = __shfl_xor_sync(0xffffffffu, v, o);
                int   oi = __shfl_xor_sync(0xffffffffu, idx, o);
                if (ov > v || (ov == v && oi < idx)) { v = ov; idx = oi; }
            }
            if (t == 0) { topl[kk] = v; topi[kk] = idx; }
            if (t == idx) lv = -INFINITY;
        }
        if (t == 0) {
            for (int kk = 0; kk < KSEL; kk++) g_head_idx[s*KSEL + kk] = topi[kk];
            g_primary[s] = topi[0];
            float m2 = topl[0], sm2 = 0.f, w[KSEL];
            for (int kk = 0; kk < KSEL; kk++) { w[kk] = expf(topl[kk] - m2); sm2 += w[kk]; }
            float inv2 = 1.f / sm2;
            for (int kk = 0; kk < KSEL; kk++) g_head_w[s*KSEL + kk] = w[kk] * inv2;
        }
    }
}

// ---------------- K2: group-by-head build (deterministic, no atomics) ----------
__global__ void k_build(const int* __restrict__ head_counts) {
    __shared__ int ccnt[8][H_];
    int t = threadIdx.x;
    int h = t & 31, ch = t >> 5;
    int c0 = ch * 1024, c1 = c0 + 1024;
    int cnt = 0;
    for (int i = c0; i < c1; i++) cnt += (g_head_idx[i] == h);
    ccnt[ch][h] = cnt;
    __syncthreads();
    if (t < 32) {
        int tot = 0;
        #pragma unroll
        for (int c = 0; c < 8; c++) tot += ccnt[c][t];
        g_nh[t] = tot;
    }
    __syncthreads();
    if (t == 0) {
        int o = 0;
        for (int hh = 0; hh < H_; hh++) { g_off[hh] = o; o += g_nh[hh]; }
        g_off[H_] = o;
        int nt = 0;
        for (int hh = 0; hh < H_; hh++) {
            for (int st = 0; st < g_nh[hh]; st += 32) {
                g_tile_head[nt] = hh;
                g_tile_start[nt] = g_off[hh] + st;
                g_tile_m[nt] = min(32, g_nh[hh] - st);
                nt++;
            }
        }
        g_ntiles = nt;
        int nt64 = 0;
        for (int hh = 0; hh < H_; hh++) {
            for (int st = 0; st < g_nh[hh]; st += 64) {
                g_t64_head[nt64] = hh;
                g_t64_start[nt64] = g_off[hh] + st;
                g_t64_m[nt64] = min(64, g_nh[hh] - st);
                nt64++;
            }
        }
        g_ntiles64 = nt64;
    }
    __syncthreads();
    int base = g_off[h];
    for (int c = 0; c < ch; c++) base += ccnt[c][h];
    int hc = head_counts[h];
    int local = 0;
    for (int i = c0; i < c1; i++) {
        if (g_head_idx[i] == h) {
            int pp = base + local;
            g_perm[pp] = i;
            g_hd[pp] = h;
            int rank = pp - g_off[h];
            int pos = rank + hc;
            pos = max(0, min(pos, MAXPOS));
            g_pos[pp] = pos;
            local++;
        }
    }
}

// ---------------- K2b: RoPE cos/sin table (double angle, reduced) --------------
__global__ void k_ropetab() {
    int j = blockIdx.x;
    int i = threadIdx.x;             // 0..63
    int pos = g_pos[j];
    double ex  = (double)(2 * i) / 128.0;
    double inv = pow(10000.0, -ex);
    double ang = (double)pos * inv;
    const double TWO_PI = 6.283185307179586476925286766559;
    double r = ang - floor(ang / TWO_PI + 0.5) * TWO_PI;   // |r| <= pi
    float fr = (float)r;
    g_cos[j*64 + i] = cosf(fr);
    g_sin[j*64 + i] = sinf(fr);
}

// ---------------- K3: grouped QKV GEMM (bf16-split tensor core) + RoPE ---------
// block: 64 tokens x 128 head-dims, K chunked by 64; grid.y = matrix (q/k/v)
// dynamic smem 48KB: Ahi[64][64]bf16 | Alo | Bhi[64][128]bf16 | Blo
// Epilogue reuses B region (32KB) as Sb[64][128] f32.
__global__ void k_qkv_mma(const float* __restrict__ x) {
    extern __shared__ unsigned char dsm[];
    __shared__ int srow[64];
    int tb = blockIdx.x;
    if (tb >= g_ntiles64) return;
    int w = blockIdx.y;
    int h     = g_t64_head[tb];
    int start = g_t64_start[tb];
    int m     = g_t64_m[tb];
    int t = threadIdx.x;
    if (t < 64) {
        int j = start + ((t < m) ? t : 0);
        srow[t] = g_perm[j] >> 3;
    }
    __syncthreads();

    int lane = t & 31, wid = t >> 5;
    int m0w = (wid & 1) * 32, n0w = (wid >> 1) * 32;
    float acc[2][4][4];
    #pragma unroll
    for (int mi = 0; mi < 2; mi++)
        #pragma unroll
        for (int nj = 0; nj < 4; nj++)
            #pragma unroll
            for (int q = 0; q < 4; q++) acc[mi][nj][q] = 0.f;

    const unsigned short* gwh = g_wh + (size_t)w * 4194304u;
    const unsigned short* gwl = g_wl + (size_t)w * 4194304u;

    unsigned smbase = (unsigned)__cvta_generic_to_shared(dsm);
    unsigned aHiB = smbase, aLoB = smbase + 8192u, bHiB = smbase + 16384u, bLoB = smbase + 32768u;

    int rowA = t >> 3, cA = t & 7;        // A staging: rows rowA, rowA+32
    int kB0 = t >> 4, cB = t & 15;        // B staging: k = kB0 + 16*kk

    for (int kc = 0; kc < E_; kc += 64) {
        __syncthreads();
        // stage A (gathered x rows, split f32 -> bf16 hi/lo), swizzled
        #pragma unroll
        for (int rr = 0; rr < 2; rr++) {
            int row = rowA + rr * 32;
            const float* xp = x + (size_t)srow[row]*E_ + kc + cA*8;
            float f[8];
            *(float4*)&f[0] = *(const float4*)xp;
            *(float4*)&f[4] = *(const float4*)(xp + 4);
            uint4 hi, lo;
            split8(f, hi, lo);
            int cp = cA ^ (row & 7);
            ((uint4*)dsm)[row*8 + cp] = hi;
            ((uint4*)(dsm + 8192))[row*8 + cp] = lo;
        }
        // stage B (precomputed bf16 hi/lo), swizzled
        #pragma unroll
        for (int kk = 0; kk < 4; kk++) {
            int k = kB0 + kk * 16;
            size_t gi = (size_t)(kc + k)*4096u + (size_t)h*128u + cB*8u;
            uint4 vh = *(const uint4*)(gwh + gi);
            uint4 vl = *(const uint4*)(gwl + gi);
            int cp = cB ^ (k & 15);
            ((uint4*)(dsm + 16384))[k*16 + cp] = vh;
            ((uint4*)(dsm + 32768))[k*16 + cp] = vl;
        }
        __syncthreads();

        #pragma unroll
        for (int s = 0; s < 4; s++) {
            unsigned ah[2][4], al[2][4];
            #pragma unroll
            for (int mi = 0; mi < 2; mi++) {
                int row = m0w + mi*16 + (lane & 7) + (lane & 8);
                int kch = 2*s + (lane >> 4);
                unsigned off = (unsigned)(row*8 + (kch ^ (row & 7))) * 16u;
                ldm4(ah[mi], aHiB + off);
                ldm4(al[mi], aLoB + off);
            }
            unsigned bh[2][4], bl[2][4];
            #pragma unroll
            for (int p = 0; p < 2; p++) {
                int k = s*16 + (lane & 7) + (lane & 8);
                int ncn = (n0w >> 3) + p*2 + (lane >> 4);
                unsigned off = (unsigned)(k*16 + (ncn ^ (k & 15))) * 16u;
                ldm4t(bh[p], bHiB + off);
                ldm4t(bl[p], bLoB + off);
            }
            #pragma unroll
            for (int mi = 0; mi < 2; mi++)
                #pragma unroll
                for (int nj = 0; nj < 4; nj++) {
                    const unsigned* Bh = &bh[nj >> 1][(nj & 1)*2];
                    const unsigned* Bl = &bl[nj >> 1][(nj & 1)*2];
                    mma16816(acc[mi][nj], ah[mi], Bh);   // hi*hi
                    mma16816(acc[mi][nj], ah[mi], Bl);   // hi*lo
                    mma16816(acc[mi][nj], al[mi], Bh);   // lo*hi
                }
        }
    }

    // epilogue: stage to smem (overlay B region), rope, store
    __syncthreads();
    float* Sb = (float*)(dsm + 16384);
    int g = lane >> 2, tt = lane & 3;
    #pragma unroll
    for (int mi = 0; mi < 2; mi++)
        #pragma unroll
        for (int nj = 0; nj < 4; nj++) {
            int r0 = m0w + mi*16 + g;
            int c0 = n0w + nj*8 + 2*tt;
            Sb[r0*128 + c0]       = acc[mi][nj][0];
            Sb[r0*128 + c0 + 1]   = acc[mi][nj][1];
            Sb[(r0+8)*128 + c0]   = acc[mi][nj][2];
            Sb[(r0+8)*128 + c0+1] = acc[mi][nj][3];
        }
    __syncthreads();
    float* dst = (w == 0) ? g_q : (w == 1) ? g_k : g_v;
    for (int idx = t; idx < 64*128; idx += 256) {
        int r = idx >> 7, c = idx & 127;
        if (r < m) {
            int j = start + r;
            float val = Sb[r*128 + c];
            float outv;
            if (w < 2) {
                int ih = c & 63;
                float cs = g_cos[j*64 + ih], sn = g_sin[j*64 + ih];
                outv = (c < 64) ? val*cs - Sb[r*128 + c + 64]*sn
                                : val*cs + Sb[r*128 + c - 64]*sn;
            } else outv = val;
            dst[(size_t)j*D_ + c] = outv;
        }
    }
}

// ---------------- K4: per-head causal attention, block per query ----------------
__global__ void k_attn() {
    extern __shared__ float sm[];
    float* sq  = sm;          // 128
    float* red = sm + 128;    // 128
    float* sc  = sm + 256;    // up to 8192 scores
    int j = blockIdx.x, t = threadIdx.x;     // 128 threads
    int h   = g_hd[j];
    int off = g_off[h];
    int nk  = j - off + 1;
    sq[t] = g_q[(size_t)j*D_ + t];
    __syncthreads();
    const float4* qr = (const float4*)sq;
    for (int kk = t; kk < nk; kk += 128) {
        const float4* kr = (const float4*)(g_k + (size_t)(off + kk)*D_);
        float d = 0.f;
        #pragma unroll
        for (int c = 0; c < 32; c++) {
            float4 kv = kr[c], qv = qr[c];
            d += qv.x*kv.x + qv.y*kv.y + qv.z*kv.z + qv.w*kv.w;
        }
        sc[kk] = d * SCALE_;
    }
    __syncthreads();
    float mx = -1e30f;
    for (int kk = t; kk < nk; kk += 128) mx = fmaxf(mx, sc[kk]);
    red[t] = mx; __syncthreads();
    for (int s2 = 64; s2; s2 >>= 1) { if (t < s2) red[t] = fmaxf(red[t], red[t + s2]); __syncthreads(); }
    mx = red[0];
    __syncthreads();
    float sume = 0.f;
    for (int kk = t; kk < nk; kk += 128) { float e2 = expf(sc[kk] - mx); sc[kk] = e2; sume += e2; }
    red[t] = sume; __syncthreads();
    for (int s2 = 64; s2; s2 >>= 1) { if (t < s2) red[t] += red[t + s2]; __syncthreads(); }
    float inv = 1.f / red[0];
    float acc = 0.f;
    for (int kk = 0; kk < nk; kk++)
        acc += sc[kk] * g_v[(size_t)(off + kk)*D_ + t];
    int e = g_perm[j];
    g_mid[(size_t)e*D_ + t] = acc * inv * g_head_w[e];
}

// ---------------- K5: output projection (bf16-split tensor core) ---------------
// out[1024,1024] = mid[1024,1024] @ Wo[1024,1024]; tiles 64(m) x 128(n), K chunk 64.
__global__ void k_out_mma(float* __restrict__ out) {
    extern __shared__ unsigned char dsm[];
    int n0 = blockIdx.x * 128;
    int m0 = blockIdx.y * 64;
    int t = threadIdx.x;
    int lane = t & 31, wid = t >> 5;
    int m0w = (wid & 1) * 32, n0w = (wid >> 1) * 32;
    float acc[2][4][4];
    #pragma unroll
    for (int mi = 0; mi < 2; mi++)
        #pragma unroll
        for (int nj = 0; nj < 4; nj++)
            #pragma unroll
            for (int q = 0; q < 4; q++) acc[mi][nj][q] = 0.f;

    unsigned smbase = (unsigned)__cvta_generic_to_shared(dsm);
    unsigned aHiB = smbase, aLoB = smbase + 8192u, bHiB = smbase + 16384u, bLoB = smbase + 32768u;

    int rowA = t >> 3, cA = t & 7;
    int kB0 = t >> 4, cB = t & 15;

    for (int kc = 0; kc < 1024; kc += 64) {
        __syncthreads();
        #pragma unroll
        for (int rr = 0; rr < 2; rr++) {
            int row = rowA + rr * 32;
            const float* xp = g_mid + (size_t)(m0 + row)*1024 + kc + cA*8;
            float f[8];
            *(float4*)&f[0] = *(const float4*)xp;
            *(float4*)&f[4] = *(const float4*)(xp + 4);
            uint4 hi, lo;
            split8(f, hi, lo);
            int cp = cA ^ (row & 7);
            ((uint4*)dsm)[row*8 + cp] = hi;
            ((uint4*)(dsm + 8192))[row*8 + cp] = lo;
        }
        #pragma unroll
        for (int kk = 0; kk < 4; kk++) {
            int k = kB0 + kk * 16;
            size_t gi = (size_t)(kc + k)*1024u + n0 + cB*8u;
            uint4 vh = *(const uint4*)(g_woh + gi);
            uint4 vl = *(const uint4*)(g_wol + gi);
            int cp = cB ^ (k & 15);
            ((uint4*)(dsm + 16384))[k*16 + cp] = vh;
            ((uint4*)(dsm + 32768))[k*16 + cp] = vl;
        }
        __syncthreads();

        #pragma unroll
        for (int s = 0; s < 4; s++) {
            unsigned ah[2][4], al[2][4];
            #pragma unroll
            for (int mi = 0; mi < 2; mi++) {
                int row = m0w + mi*16 + (lane & 7) + (lane & 8);
                int kch = 2*s + (lane >> 4);
                unsigned off = (unsigned)(row*8 + (kch ^ (row & 7))) * 16u;
                ldm4(ah[mi], aHiB + off);
                ldm4(al[mi], aLoB + off);
            }
            unsigned bh[2][4], bl[2][4];
            #pragma unroll
            for (int p = 0; p < 2; p++) {
                int k = s*16 + (lane & 7) + (lane & 8);
                int ncn = (n0w >> 3) + p*2 + (lane >> 4);
                unsigned off = (unsigned)(k*16 + (ncn ^ (k & 15))) * 16u;
                ldm4t(bh[p], bHiB + off);
                ldm4t(bl[p], bLoB + off);
            }
            #pragma unroll
            for (int mi = 0; mi < 2; mi++)
                #pragma unroll
                for (int nj = 0; nj < 4; nj++) {
                    const unsigned* Bh = &bh[nj >> 1][(nj & 1)*2];
                    const unsigned* Bl = &bl[nj >> 1][(nj & 1)*2];
                    mma16816(acc[mi][nj], ah[mi], Bh);
                    mma16816(acc[mi][nj], ah[mi], Bl);
                    mma16816(acc[mi][nj], al[mi], Bh);
                }
        }
    }

    int g = lane >> 2, tt = lane & 3;
    #pragma unroll
    for (int mi = 0; mi < 2; mi++)
        #pragma unroll
        for (int nj = 0; nj < 4; nj++) {
            int r = m0 + m0w + mi*16 + g;
            int c = n0 + n0w + nj*8 + 2*tt;
            *(float2*)&out[(size_t)r*1024 + c]     = make_float2(acc[mi][nj][0], acc[mi][nj][1]);
            *(float2*)&out[(size_t)(r+8)*1024 + c] = make_float2(acc[mi][nj][2], acc[mi][nj][3]);
        }
}

// ---------------- K6: counts + aux loss (deterministic reductions) --------------
__global__ void k_final(const int* __restrict__ head_counts, float* __restrict__ out, int out_size) {
    __shared__ float fb[H_];
    int t = threadIdx.x;   // 32 threads
    float psum = 0.f; int fcnt = 0;
    for (int s = 0; s < S_; s++) {
        psum += g_probs[s*H_ + t];
        fcnt += (g_primary[s] == t);
    }
    float f = (float)fcnt / (float)S_;
    float p = psum / (float)S_;
    fb[t] = f * p;
    if (out_size >= S_*E_ + H_)
        out[S_*E_ + t] = (float)(g_nh[t] + head_counts[t]);
    float es = 0.f, zs = 0.f;
    for (int s = t; s < S_; s += 32) { es += g_ent[s]; zs += g_z[s]; }
    for (int o = 16; o; o >>= 1) {
        es += __shfl_xor_sync(0xffffffffu, es, o);
        zs += __shfl_xor_sync(0xffffffffu, zs, o);
    }
    __syncwarp();
    if (t == 0) {
        float bal = 0.f;
        for (int hh = 0; hh < H_; hh++) bal += fb[hh];
        bal *= (float)H_;
        float ent_loss = -es / (float)S_;
        float z_loss   = (zs / (float)S_) * 0.01f;
        float aux = 0.01f * bal + 0.01f * ent_loss + z_loss;
        if (out_size >= S_*E_ + H_ + 1) out[S_*E_ + H_] = aux;
    }
}

// ---------------- launch ---------------------------------------------------------
extern "C" void kernel_launch(void* const* d_in, const int* in_sizes, int n_in,
                              void* d_out, int out_size) {
    const float* x  = (const float*)d_in[0];
    const float* Wq = (const float*)d_in[1];
    const float* Wk = (const float*)d_in[2];
    const float* Wv = (const float*)d_in[3];
    const float* Wr = (const float*)d_in[4];
    const float* Wo = (const float*)d_in[5];
    const int*   hc = (const int*)d_in[6];
    float* out = (float*)d_out;

    cudaFuncSetAttribute(k_qkv_mma, cudaFuncAttributeMaxDynamicSharedMemorySize, 49152);
    cudaFuncSetAttribute(k_out_mma, cudaFuncAttributeMaxDynamicSharedMemorySize, 49152);

    k_router<<<S_, 256>>>(x, Wr);
    k_split<<<13312, 256>>>(Wq, Wk, Wv, Wo);
    k_build<<<1, 256>>>(hc);
    k_ropetab<<<NE, 64>>>();
    k_qkv_mma<<<dim3(160, 3), 256, 49152>>>(x);
    k_attn<<<NE, 128, (256 + NE) * sizeof(float)>>>();
    k_out_mma<<<dim3(8, 16), 256, 49152>>>(out);
    k_final<<<1, 32>>>(hc, out, out_size);
}

// round 3
// speedup vs baseline: 1.5774x; 1.1782x over previous
#include <cuda_runtime.h>
#include <cuda_bf16.h>
#include <math.h>

#define S_    1024
#define H_    32
#define KSEL  8
#define D_    128
#define E_    1024
#define NE    (S_*KSEL)       // 8192
#define SCALE_ 0.08838834764831845f   // 128^-0.5
#define MAXPOS 8191

// ---------------- scratch (static device globals; no allocation) ----------------
__device__ float g_q[NE*D_];
__device__ float g_k[NE*D_];
__device__ float g_v[NE*D_];
__device__ float g_mid[S_*E_];
__device__ int   g_head_idx[NE];
__device__ float g_head_w[NE];
__device__ float g_probs[S_*H_];
__device__ float g_ent[S_];
__device__ float g_z[S_];
__device__ int   g_primary[S_];
__device__ int   g_nh[H_];
__device__ int   g_off[H_+1];
__device__ int   g_perm[NE];
__device__ int   g_hd[NE];
__device__ int   g_pos[NE];
__device__ float g_cos[NE*64];
__device__ float g_sin[NE*64];
__device__ double g_invf[64];
__device__ int   g_tile_head[300];
__device__ int   g_tile_start[300];
__device__ int   g_tile_m[300];
__device__ int   g_ntiles;
__device__ int   g_t64_head[176];
__device__ int   g_t64_start[176];
__device__ int   g_t64_m[176];
__device__ int   g_ntiles64;

// split-bf16 weights (hi/lo). Layouts match the source fp32 matrices.
__device__ unsigned short g_wh[3u*1024u*4096u];   // Wq,Wk,Wv hi
__device__ unsigned short g_wl[3u*1024u*4096u];   // lo
__device__ unsigned short g_woh[1024u*1024u];     // Wo hi
__device__ unsigned short g_wol[1024u*1024u];     // lo

// ---------------- mma helpers ---------------------------------------------------
__device__ __forceinline__ void ldm4(unsigned r[4], unsigned a) {
    asm volatile("ldmatrix.sync.aligned.m8n8.x4.shared.b16 {%0,%1,%2,%3},[%4];"
        : "=r"(r[0]), "=r"(r[1]), "=r"(r[2]), "=r"(r[3]) : "r"(a));
}
__device__ __forceinline__ void ldm4t(unsigned r[4], unsigned a) {
    asm volatile("ldmatrix.sync.aligned.m8n8.x4.trans.shared.b16 {%0,%1,%2,%3},[%4];"
        : "=r"(r[0]), "=r"(r[1]), "=r"(r[2]), "=r"(r[3]) : "r"(a));
}
__device__ __forceinline__ void mma16816(float d[4], const unsigned a[4], const unsigned b[2]) {
    asm volatile("mma.sync.aligned.m16n8k16.row.col.f32.bf16.bf16.f32 "
        "{%0,%1,%2,%3},{%4,%5,%6,%7},{%8,%9},{%0,%1,%2,%3};"
        : "+f"(d[0]), "+f"(d[1]), "+f"(d[2]), "+f"(d[3])
        : "r"(a[0]), "r"(a[1]), "r"(a[2]), "r"(a[3]), "r"(b[0]), "r"(b[1]));
}
__device__ __forceinline__ void split8(const float* f, uint4& h, uint4& l) {
    unsigned hu[4], lu[4];
    #pragma unroll
    for (int i = 0; i < 4; i++) {
        float a = f[2*i], b = f[2*i+1];
        __nv_bfloat16 ha = __float2bfloat16(a), hb = __float2bfloat16(b);
        float ra = a - __bfloat162float(ha), rb = b - __bfloat162float(hb);
        __nv_bfloat16 la = __float2bfloat16(ra), lb = __float2bfloat16(rb);
        hu[i] = (unsigned)__bfloat16_as_ushort(ha) | ((unsigned)__bfloat16_as_ushort(hb) << 16);
        lu[i] = (unsigned)__bfloat16_as_ushort(la) | ((unsigned)__bfloat16_as_ushort(lb) << 16);
    }
    h = make_uint4(hu[0], hu[1], hu[2], hu[3]);
    l = make_uint4(lu[0], lu[1], lu[2], lu[3]);
}

// ---------------- K0: split weights into bf16 hi/lo ------------------------------
__global__ void k_split(const float* __restrict__ Wq, const float* __restrict__ Wk,
                        const float* __restrict__ Wv, const float* __restrict__ Wo) {
    const unsigned WQKV4 = 3u*1024u*4096u/4u;
    unsigned i4 = blockIdx.x*256u + threadIdx.x;
    const float* src;
    unsigned e4;
    unsigned short *dh, *dl;
    unsigned di;
    if (i4 < WQKV4) {
        unsigned w = i4 / 1048576u;
        e4 = i4 % 1048576u;
        src = (w == 0) ? Wq : (w == 1) ? Wk : Wv;
        dh = g_wh; dl = g_wl; di = i4;
    } else {
        e4 = i4 - WQKV4;
        src = Wo;
        dh = g_woh; dl = g_wol; di = e4;
    }
    float4 v = ((const float4*)src)[e4];
    float f[4] = {v.x, v.y, v.z, v.w};
    unsigned hu[2], lu[2];
    #pragma unroll
    for (int i = 0; i < 2; i++) {
        float a = f[2*i], b = f[2*i+1];
        __nv_bfloat16 ha = __float2bfloat16(a), hb = __float2bfloat16(b);
        float ra = a - __bfloat162float(ha), rb = b - __bfloat162float(hb);
        __nv_bfloat16 la = __float2bfloat16(ra), lb = __float2bfloat16(rb);
        hu[i] = (unsigned)__bfloat16_as_ushort(ha) | ((unsigned)__bfloat16_as_ushort(hb) << 16);
        lu[i] = (unsigned)__bfloat16_as_ushort(la) | ((unsigned)__bfloat16_as_ushort(lb) << 16);
    }
    ((uint2*)dh)[di] = make_uint2(hu[0], hu[1]);
    ((uint2*)dl)[di] = make_uint2(lu[0], lu[1]);
}

// ---------------- K1: router — logits, softmax stats, top-8, head weights ------
__global__ void k_router(const float* __restrict__ x, const float* __restrict__ Wr) {
    __shared__ float xs[E_];
    __shared__ float part[8][H_];
    int s = blockIdx.x, t = threadIdx.x;
    for (int i = t; i < E_; i += 256) xs[i] = x[s*E_ + i];
    __syncthreads();
    int c = t & 31, pr = t >> 5;
    float acc = 0.f;
    int e0 = pr * 128;
    #pragma unroll 4
    for (int e = e0; e < e0 + 128; e++) acc += xs[e] * Wr[e*H_ + c];
    part[pr][c] = acc;
    __syncthreads();
    if (t < 32) {
        float l = 0.f;
        #pragma unroll
        for (int p = 0; p < 8; p++) l += part[p][t];
        float m = l;
        for (int o = 16; o; o >>= 1) m = fmaxf(m, __shfl_xor_sync(0xffffffffu, m, o));
        float ex = expf(l - m);
        float sum = ex;
        for (int o = 16; o; o >>= 1) sum += __shfl_xor_sync(0xffffffffu, sum, o);
        float p = ex / sum;
        g_probs[s*H_ + t] = p;
        float et = p * logf(p + 1e-8f);
        float ent = et;
        for (int o = 16; o; o >>= 1) ent += __shfl_xor_sync(0xffffffffu, ent, o);
        if (t == 0) {
            g_ent[s] = -ent;
            float lse = m + logf(sum);
            g_z[s] = lse * lse;
        }
        float lv = l;
        float topl[KSEL];
        int   topi[KSEL];
        for (int kk = 0; kk < KSEL; kk++) {
            float v = lv; int idx = t;
            for (int o = 16; o; o >>= 1) {
                float ov = __shfl_xor_sync(0xffffffffu, v, o);
                int   oi = __shfl_xor_sync(0xffffffffu, idx, o);
                if (ov > v || (ov == v && oi < idx)) { v = ov; idx = oi; }
            }
            if (t == 0) { topl[kk] = v; topi[kk] = idx; }
            if (t == idx) lv = -INFINITY;
        }
        if (t == 0) {
            for (int kk = 0; kk < KSEL; kk++) g_head_idx[s*KSEL + kk] = topi[kk];
            g_primary[s] = topi[0];
            float m2 = topl[0], sm2 = 0.f, w[KSEL];
            for (int kk = 0; kk < KSEL; kk++) { w[kk] = expf(topl[kk] - m2); sm2 += w[kk]; }
            float inv2 = 1.f / sm2;
            for (int kk = 0; kk < KSEL; kk++) g_head_w[s*KSEL + kk] = w[kk] * inv2;
        }
    }
}

// ---------------- K2: group-by-head build (deterministic, no atomics) ----------
__global__ void k_build(const int* __restrict__ head_counts) {
    __shared__ int ccnt[8][H_];
    int t = threadIdx.x;
    int h = t & 31, ch = t >> 5;
    int c0 = ch * 1024, c1 = c0 + 1024;
    int cnt = 0;
    for (int i = c0; i < c1; i++) cnt += (g_head_idx[i] == h);
    ccnt[ch][h] = cnt;
    __syncthreads();
    if (t < 32) {
        int tot = 0;
        #pragma unroll
        for (int c = 0; c < 8; c++) tot += ccnt[c][t];
        g_nh[t] = tot;
    }
    __syncthreads();
    if (t == 0) {
        int o = 0;
        for (int hh = 0; hh < H_; hh++) { g_off[hh] = o; o += g_nh[hh]; }
        g_off[H_] = o;
        int nt = 0;
        for (int hh = 0; hh < H_; hh++) {
            for (int st = 0; st < g_nh[hh]; st += 32) {
                g_tile_head[nt] = hh;
                g_tile_start[nt] = g_off[hh] + st;
                g_tile_m[nt] = min(32, g_nh[hh] - st);
                nt++;
            }
        }
        g_ntiles = nt;
        int nt64 = 0;
        for (int hh = 0; hh < H_; hh++) {
            for (int st = 0; st < g_nh[hh]; st += 64) {
                g_t64_head[nt64] = hh;
                g_t64_start[nt64] = g_off[hh] + st;
                g_t64_m[nt64] = min(64, g_nh[hh] - st);
                nt64++;
            }
        }
        g_ntiles64 = nt64;
    }
    __syncthreads();
    int base = g_off[h];
    for (int c = 0; c < ch; c++) base += ccnt[c][h];
    int hc = head_counts[h];
    int local = 0;
    for (int i = c0; i < c1; i++) {
        if (g_head_idx[i] == h) {
            int pp = base + local;
            g_perm[pp] = i;
            g_hd[pp] = h;
            int rank = pp - g_off[h];
            int pos = rank + hc;
            pos = max(0, min(pos, MAXPOS));
            g_pos[pp] = pos;
            local++;
        }
    }
}

// ---------------- K2a: inverse-frequency table (64 doubles, once) ----------------
__global__ void k_invf() {
    int i = threadIdx.x;
    double ex = (double)(2 * i) / 128.0;
    g_invf[i] = pow(10000.0, -ex);
}

// ---------------- K2b: RoPE cos/sin table (DP multiply only) --------------------
__global__ void k_ropetab() {
    int idx = blockIdx.x * 256 + threadIdx.x;   // 2048 x 256 = 524288
    int j = idx >> 6, i = idx & 63;
    double ang = (double)g_pos[j] * g_invf[i];
    const double TWO_PI = 6.283185307179586476925286766559;
    double r = ang - floor(ang / TWO_PI + 0.5) * TWO_PI;   // |r| <= pi
    float fr = (float)r;
    g_cos[j*64 + i] = cosf(fr);
    g_sin[j*64 + i] = sinf(fr);
}

// ---------------- K3: grouped QKV GEMM (bf16-split tensor core) + RoPE ---------
__global__ void k_qkv_mma(const float* __restrict__ x) {
    extern __shared__ unsigned char dsm[];
    __shared__ int srow[64];
    int tb = blockIdx.x;
    if (tb >= g_ntiles64) return;
    int w = blockIdx.y;
    int h     = g_t64_head[tb];
    int start = g_t64_start[tb];
    int m     = g_t64_m[tb];
    int t = threadIdx.x;
    if (t < 64) {
        int j = start + ((t < m) ? t : 0);
        srow[t] = g_perm[j] >> 3;
    }
    __syncthreads();

    int lane = t & 31, wid = t >> 5;
    int m0w = (wid & 1) * 32, n0w = (wid >> 1) * 32;
    float acc[2][4][4];
    #pragma unroll
    for (int mi = 0; mi < 2; mi++)
        #pragma unroll
        for (int nj = 0; nj < 4; nj++)
            #pragma unroll
            for (int q = 0; q < 4; q++) acc[mi][nj][q] = 0.f;

    const unsigned short* gwh = g_wh + (size_t)w * 4194304u;
    const unsigned short* gwl = g_wl + (size_t)w * 4194304u;

    unsigned smbase = (unsigned)__cvta_generic_to_shared(dsm);
    unsigned aHiB = smbase, aLoB = smbase + 8192u, bHiB = smbase + 16384u, bLoB = smbase + 32768u;

    int rowA = t >> 3, cA = t & 7;
    int kB0 = t >> 4, cB = t & 15;

    for (int kc = 0; kc < E_; kc += 64) {
        __syncthreads();
        #pragma unroll
        for (int rr = 0; rr < 2; rr++) {
            int row = rowA + rr * 32;
            const float* xp = x + (size_t)srow[row]*E_ + kc + cA*8;
            float f[8];
            *(float4*)&f[0] = *(const float4*)xp;
            *(float4*)&f[4] = *(const float4*)(xp + 4);
            uint4 hi, lo;
            split8(f, hi, lo);
            int cp = cA ^ (row & 7);
            ((uint4*)dsm)[row*8 + cp] = hi;
            ((uint4*)(dsm + 8192))[row*8 + cp] = lo;
        }
        #pragma unroll
        for (int kk = 0; kk < 4; kk++) {
            int k = kB0 + kk * 16;
            size_t gi = (size_t)(kc + k)*4096u + (size_t)h*128u + cB*8u;
            uint4 vh = *(const uint4*)(gwh + gi);
            uint4 vl = *(const uint4*)(gwl + gi);
            int cp = cB ^ (k & 15);
            ((uint4*)(dsm + 16384))[k*16 + cp] = vh;
            ((uint4*)(dsm + 32768))[k*16 + cp] = vl;
        }
        __syncthreads();

        #pragma unroll
        for (int s = 0; s < 4; s++) {
            unsigned ah[2][4], al[2][4];
            #pragma unroll
            for (int mi = 0; mi < 2; mi++) {
                int row = m0w + mi*16 + (lane & 7) + (lane & 8);
                int kch = 2*s + (lane >> 4);
                unsigned off = (unsigned)(row*8 + (kch ^ (row & 7))) * 16u;
                ldm4(ah[mi], aHiB + off);
                ldm4(al[mi], aLoB + off);
            }
            unsigned bh[2][4], bl[2][4];
            #pragma unroll
            for (int p = 0; p < 2; p++) {
                int k = s*16 + (lane & 7) + (lane & 8);
                int ncn = (n0w >> 3) + p*2 + (lane >> 4);
                unsigned off = (unsigned)(k*16 + (ncn ^ (k & 15))) * 16u;
                ldm4t(bh[p], bHiB + off);
                ldm4t(bl[p], bLoB + off);
            }
            #pragma unroll
            for (int mi = 0; mi < 2; mi++)
                #pragma unroll
                for (int nj = 0; nj < 4; nj++) {
                    const unsigned* Bh = &bh[nj >> 1][(nj & 1)*2];
                    const unsigned* Bl = &bl[nj >> 1][(nj & 1)*2];
                    mma16816(acc[mi][nj], ah[mi], Bh);
                    mma16816(acc[mi][nj], ah[mi], Bl);
                    mma16816(acc[mi][nj], al[mi], Bh);
                }
        }
    }

    __syncthreads();
    float* Sb = (float*)(dsm + 16384);
    int g = lane >> 2, tt = lane & 3;
    #pragma unroll
    for (int mi = 0; mi < 2; mi++)
        #pragma unroll
        for (int nj = 0; nj < 4; nj++) {
            int r0 = m0w + mi*16 + g;
            int c0 = n0w + nj*8 + 2*tt;
            Sb[r0*128 + c0]       = acc[mi][nj][0];
            Sb[r0*128 + c0 + 1]   = acc[mi][nj][1];
            Sb[(r0+8)*128 + c0]   = acc[mi][nj][2];
            Sb[(r0+8)*128 + c0+1] = acc[mi][nj][3];
        }
    __syncthreads();
    float* dst = (w == 0) ? g_q : (w == 1) ? g_k : g_v;
    for (int idx = t; idx < 64*128; idx += 256) {
        int r = idx >> 7, c = idx & 127;
        if (r < m) {
            int j = start + r;
            float val = Sb[r*128 + c];
            float outv;
            if (w < 2) {
                int ih = c & 63;
                float cs = g_cos[j*64 + ih], sn = g_sin[j*64 + ih];
                outv = (c < 64) ? val*cs - Sb[r*128 + c + 64]*sn
                                : val*cs + Sb[r*128 + c - 64]*sn;
            } else outv = val;
            dst[(size_t)j*D_ + c] = outv;
        }
    }
}

// ---------------- K4: tiled flash-style per-head causal attention --------------
// block = one 32-query tile; online softmax over 32-key chunks staged in smem.
#define AQS 132   // padded f32 row stride
__global__ void k_attn2() {
    extern __shared__ float asm_[];
    float* Qs = asm_;                 // [32][AQS]
    float* Ks = asm_ + 32*AQS;        // [32][AQS]
    float* Vs = asm_ + 64*AQS;        // [32][AQS]
    float* Ps = asm_ + 96*AQS;        // [32][33]
    __shared__ float s_m[32], s_l[32], s_scale[32];

    int tb = blockIdx.x;
    if (tb >= g_ntiles) return;
    int h = g_tile_head[tb], start = g_tile_start[tb], m = g_tile_m[tb];
    int off = g_off[h];
    int t = threadIdx.x;

    // load Q tile (32 rows; dup last valid row for r >= m)
    for (int idx = t; idx < 32*32; idx += 256) {
        int r = idx >> 5, c4 = idx & 31;
        int j = start + ((r < m) ? r : (m - 1));
        *(float4*)&Qs[r*AQS + c4*4] = *(const float4*)&g_q[(size_t)j*D_ + c4*4];
    }
    if (t < 32) { s_m[t] = -1e30f; s_l[t] = 0.f; s_scale[t] = 1.f; }

    float acc[16];
    #pragma unroll
    for (int i = 0; i < 16; i++) acc[i] = 0.f;
    int qa = t >> 3, db = (t & 7) * 16;      // PV mapping
    int q0 = (t >> 4) * 2;                   // score mapping: 2 queries
    int k0 = t & 15, k1 = k0 + 16;           // 2 keys (stride-16)

    int kend = start + m;
    for (int koff = off; koff < kend; koff += 32) {
        int kn = min(32, kend - koff);
        __syncthreads();
        for (int idx = t; idx < 32*32; idx += 256) {
            int r = idx >> 5, c4 = idx & 31;
            int kj = koff + ((r < kn) ? r : (kn - 1));
            *(float4*)&Ks[r*AQS + c4*4] = *(const float4*)&g_k[(size_t)kj*D_ + c4*4];
            *(float4*)&Vs[r*AQS + c4*4] = *(const float4*)&g_v[(size_t)kj*D_ + c4*4];
        }
        __syncthreads();
        // scores: 2 queries x 2 keys per thread
        float s00 = 0.f, s01 = 0.f, s10 = 0.f, s11 = 0.f;
        #pragma unroll 8
        for (int c = 0; c < 128; c += 4) {
            float4 a0 = *(float4*)&Qs[q0*AQS + c];
            float4 a1 = *(float4*)&Qs[(q0+1)*AQS + c];
            float4 b0 = *(float4*)&Ks[k0*AQS + c];
            float4 b1 = *(float4*)&Ks[k1*AQS + c];
            s00 += a0.x*b0.x + a0.y*b0.y + a0.z*b0.z + a0.w*b0.w;
            s01 += a0.x*b1.x + a0.y*b1.y + a0.z*b1.z + a0.w*b1.w;
            s10 += a1.x*b0.x + a1.y*b0.y + a1.z*b0.z + a1.w*b0.w;
            s11 += a1.x*b1.x + a1.y*b1.y + a1.z*b1.z + a1.w*b1.w;
        }
        {
            int jq0 = start + q0, jq1 = jq0 + 1;
            int kg0 = koff + k0, kg1 = koff + k1;
            Ps[q0*33 + k0]     = (k0 < kn && kg0 <= jq0) ? s00*SCALE_ : -1e30f;
            Ps[q0*33 + k1]     = (k1 < kn && kg1 <= jq0) ? s01*SCALE_ : -1e30f;
            Ps[(q0+1)*33 + k0] = (k0 < kn && kg0 <= jq1) ? s10*SCALE_ : -1e30f;
            Ps[(q0+1)*33 + k1] = (k1 < kn && kg1 <= jq1) ? s11*SCALE_ : -1e30f;
        }
        __syncthreads();
        // per-row online softmax (threads 0..31, one query each)
        if (t < 32) {
            float mo = s_m[t];
            float mx = mo;
            #pragma unroll 8
            for (int k = 0; k < 32; k++) mx = fmaxf(mx, Ps[t*33 + k]);
            float sc = expf(mo - mx);
            float l = s_l[t] * sc;
            #pragma unroll 8
            for (int k = 0; k < 32; k++) {
                float e = expf(Ps[t*33 + k] - mx);
                Ps[t*33 + k] = e;
                l += e;
            }
            s_m[t] = mx; s_l[t] = l; s_scale[t] = sc;
        }
        __syncthreads();
        // PV accumulate: thread = (query qa, 16 dims at db)
        float sc = s_scale[qa];
        #pragma unroll
        for (int i = 0; i < 16; i++) acc[i] *= sc;
        for (int k = 0; k < kn; k++) {
            float p = Ps[qa*33 + k];
            #pragma unroll
            for (int c4 = 0; c4 < 4; c4++) {
                float4 v = *(float4*)&Vs[k*AQS + db + c4*4];
                acc[c4*4+0] += p * v.x;
                acc[c4*4+1] += p * v.y;
                acc[c4*4+2] += p * v.z;
                acc[c4*4+3] += p * v.w;
            }
        }
    }
    __syncthreads();
    if (qa < m) {
        int j = start + qa;
        int e = g_perm[j];
        float wsc = g_head_w[e] / s_l[qa];
        #pragma unroll
        for (int c4 = 0; c4 < 4; c4++) {
            float4 o;
            o.x = acc[c4*4+0] * wsc;
            o.y = acc[c4*4+1] * wsc;
            o.z = acc[c4*4+2] * wsc;
            o.w = acc[c4*4+3] * wsc;
            *(float4*)&g_mid[(size_t)e*D_ + db + c4*4] = o;
        }
    }
}

// ---------------- K5: output projection (bf16-split tensor core) ---------------
__global__ void k_out_mma(float* __restrict__ out) {
    extern __shared__ unsigned char dsm[];
    int n0 = blockIdx.x * 128;
    int m0 = blockIdx.y * 64;
    int t = threadIdx.x;
    int lane = t & 31, wid = t >> 5;
    int m0w = (wid & 1) * 32, n0w = (wid >> 1) * 32;
    float acc[2][4][4];
    #pragma unroll
    for (int mi = 0; mi < 2; mi++)
        #pragma unroll
        for (int nj = 0; nj < 4; nj++)
            #pragma unroll
            for (int q = 0; q < 4; q++) acc[mi][nj][q] = 0.f;

    unsigned smbase = (unsigned)__cvta_generic_to_shared(dsm);
    unsigned aHiB = smbase, aLoB = smbase + 8192u, bHiB = smbase + 16384u, bLoB = smbase + 32768u;

    int rowA = t >> 3, cA = t & 7;
    int kB0 = t >> 4, cB = t & 15;

    for (int kc = 0; kc < 1024; kc += 64) {
        __syncthreads();
        #pragma unroll
        for (int rr = 0; rr < 2; rr++) {
            int row = rowA + rr * 32;
            const float* xp = g_mid + (size_t)(m0 + row)*1024 + kc + cA*8;
            float f[8];
            *(float4*)&f[0] = *(const float4*)xp;
            *(float4*)&f[4] = *(const float4*)(xp + 4);
            uint4 hi, lo;
            split8(f, hi, lo);
            int cp = cA ^ (row & 7);
            ((uint4*)dsm)[row*8 + cp] = hi;
            ((uint4*)(dsm + 8192))[row*8 + cp] = lo;
        }
        #pragma unroll
        for (int kk = 0; kk < 4; kk++) {
            int k = kB0 + kk * 16;
            size_t gi = (size_t)(kc + k)*1024u + n0 + cB*8u;
            uint4 vh = *(const uint4*)(g_woh + gi);
            uint4 vl = *(const uint4*)(g_wol + gi);
            int cp = cB ^ (k & 15);
            ((uint4*)(dsm + 16384))[k*16 + cp] = vh;
            ((uint4*)(dsm + 32768))[k*16 + cp] = vl;
        }
        __syncthreads();

        #pragma unroll
        for (int s = 0; s < 4; s++) {
            unsigned ah[2][4], al[2][4];
            #pragma unroll
            for (int mi = 0; mi < 2; mi++) {
                int row = m0w + mi*16 + (lane & 7) + (lane & 8);
                int kch = 2*s + (lane >> 4);
                unsigned off = (unsigned)(row*8 + (kch ^ (row & 7))) * 16u;
                ldm4(ah[mi], aHiB + off);
                ldm4(al[mi], aLoB + off);
            }
            unsigned bh[2][4], bl[2][4];
            #pragma unroll
            for (int p = 0; p < 2; p++) {
                int k = s*16 + (lane & 7) + (lane & 8);
                int ncn = (n0w >> 3) + p*2 + (lane >> 4);
                unsigned off = (unsigned)(k*16 + (ncn ^ (k & 15))) * 16u;
                ldm4t(bh[p], bHiB + off);
                ldm4t(bl[p], bLoB + off);
            }
            #pragma unroll
            for (int mi = 0; mi < 2; mi++)
                #pragma unroll
                for (int nj = 0; nj < 4; nj++) {
                    const unsigned* Bh = &bh[nj >> 1][(nj & 1)*2];
                    const unsigned* Bl = &bl[nj >> 1][(nj & 1)*2];
                    mma16816(acc[mi][nj], ah[mi], Bh);
                    mma16816(acc[mi][nj], ah[mi], Bl);
                    mma16816(acc[mi][nj], al[mi], Bh);
                }
        }
    }

    int g = lane >> 2, tt = lane & 3;
    #pragma unroll
    for (int mi = 0; mi < 2; mi++)
        #pragma unroll
        for (int nj = 0; nj < 4; nj++) {
            int r = m0 + m0w + mi*16 + g;
            int c = n0 + n0w + nj*8 + 2*tt;
            *(float2*)&out[(size_t)r*1024 + c]     = make_float2(acc[mi][nj][0], acc[mi][nj][1]);
            *(float2*)&out[(size_t)(r+8)*1024 + c] = make_float2(acc[mi][nj][2], acc[mi][nj][3]);
        }
}

// ---------------- K6: counts + aux loss (deterministic reductions) --------------
__global__ void k_final(const int* __restrict__ head_counts, float* __restrict__ out, int out_size) {
    __shared__ float fb[H_];
    int t = threadIdx.x;   // 32 threads
    float psum = 0.f; int fcnt = 0;
    for (int s = 0; s < S_; s++) {
        psum += g_probs[s*H_ + t];
        fcnt += (g_primary[s] == t);
    }
    float f = (float)fcnt / (float)S_;
    float p = psum / (float)S_;
    fb[t] = f * p;
    if (out_size >= S_*E_ + H_)
        out[S_*E_ + t] = (float)(g_nh[t] + head_counts[t]);
    float es = 0.f, zs = 0.f;
    for (int s = t; s < S_; s += 32) { es += g_ent[s]; zs += g_z[s]; }
    for (int o = 16; o; o >>= 1) {
        es += __shfl_xor_sync(0xffffffffu, es, o);
        zs += __shfl_xor_sync(0xffffffffu, zs, o);
    }
    __syncwarp();
    if (t == 0) {
        float bal = 0.f;
        for (int hh = 0; hh < H_; hh++) bal += fb[hh];
        bal *= (float)H_;
        float ent_loss = -es / (float)S_;
        float z_loss   = (zs / (float)S_) * 0.01f;
        float aux = 0.01f * bal + 0.01f * ent_loss + z_loss;
        if (out_size >= S_*E_ + H_ + 1) out[S_*E_ + H_] = aux;
    }
}

// ---------------- launch ---------------------------------------------------------
extern "C" void kernel_launch(void* const* d_in, const int* in_sizes, int n_in,
                              void* d_out, int out_size) {
    const float* x  = (const float*)d_in[0];
    const float* Wq = (const float*)d_in[1];
    const float* Wk = (const float*)d_in[2];
    const float* Wv = (const float*)d_in[3];
    const float* Wr = (const float*)d_in[4];
    const float* Wo = (const float*)d_in[5];
    const int*   hc = (const int*)d_in[6];
    float* out = (float*)d_out;

    const int attn_smem = (96*AQS + 32*33) * 4;   // Q,K,V + P  (~55KB)

    cudaFuncSetAttribute(k_qkv_mma, cudaFuncAttributeMaxDynamicSharedMemorySize, 49152);
    cudaFuncSetAttribute(k_out_mma, cudaFuncAttributeMaxDynamicSharedMemorySize, 49152);
    cudaFuncSetAttribute(k_attn2,  cudaFuncAttributeMaxDynamicSharedMemorySize, 57344);

    k_router<<<S_, 256>>>(x, Wr);
    k_split<<<13312, 256>>>(Wq, Wk, Wv, Wo);
    k_build<<<1, 256>>>(hc);
    k_invf<<<1, 64>>>();
    k_ropetab<<<2048, 256>>>();
    k_qkv_mma<<<dim3(160, 3), 256, 49152>>>(x);
    k_attn2<<<300, 256, attn_smem>>>();
    k_out_mma<<<dim3(8, 16), 256, 49152>>>(out);
    k_final<<<1, 32>>>(hc, out, out_size);
}

// round 4
// speedup vs baseline: 2.5887x; 1.6412x over previous
#include <cuda_runtime.h>
#include <cuda_bf16.h>
#include <math.h>

#define S_    1024
#define H_    32
#define KSEL  8
#define D_    128
#define E_    1024
#define NE    (S_*KSEL)       // 8192
#define SCALE_ 0.08838834764831845f   // 128^-0.5
#define MAXPOS 8191

// ---------------- scratch (static device globals; no allocation) ----------------
__device__ unsigned short g_qh[NE*D_], g_ql[NE*D_];
__device__ unsigned short g_kh[NE*D_], g_kl[NE*D_];
__device__ unsigned short g_vh[NE*D_], g_vl[NE*D_];
__device__ float g_mid[S_*E_];
__device__ int   g_head_idx[NE];
__device__ float g_head_w[NE];
__device__ float g_probs[S_*H_];
__device__ float g_ent[S_];
__device__ float g_z[S_];
__device__ int   g_primary[S_];
__device__ int   g_nh[H_];
__device__ int   g_off[H_+1];
__device__ int   g_perm[NE];
__device__ int   g_pos[NE];
__device__ float g_cos[NE*64];
__device__ float g_sin[NE*64];
__device__ int   g_tile_head[300];
__device__ int   g_tile_start[300];
__device__ int   g_tile_m[300];
__device__ int   g_ntiles;
__device__ int   g_t64_head[176];
__device__ int   g_t64_start[176];
__device__ int   g_t64_m[176];
__device__ int   g_ntiles64;

__device__ unsigned short g_woh[1024u*1024u];     // Wo hi
__device__ unsigned short g_wol[1024u*1024u];     // lo

// ---------------- mma helpers ---------------------------------------------------
__device__ __forceinline__ void ldm4(unsigned r[4], unsigned a) {
    asm volatile("ldmatrix.sync.aligned.m8n8.x4.shared.b16 {%0,%1,%2,%3},[%4];"
        : "=r"(r[0]), "=r"(r[1]), "=r"(r[2]), "=r"(r[3]) : "r"(a));
}
__device__ __forceinline__ void ldm4t(unsigned r[4], unsigned a) {
    asm volatile("ldmatrix.sync.aligned.m8n8.x4.trans.shared.b16 {%0,%1,%2,%3},[%4];"
        : "=r"(r[0]), "=r"(r[1]), "=r"(r[2]), "=r"(r[3]) : "r"(a));
}
__device__ __forceinline__ void ldm2(unsigned r[2], unsigned a) {
    asm volatile("ldmatrix.sync.aligned.m8n8.x2.shared.b16 {%0,%1},[%2];"
        : "=r"(r[0]), "=r"(r[1]) : "r"(a));
}
__device__ __forceinline__ void mma16816(float d[4], const unsigned a[4], const unsigned b[2]) {
    asm volatile("mma.sync.aligned.m16n8k16.row.col.f32.bf16.bf16.f32 "
        "{%0,%1,%2,%3},{%4,%5,%6,%7},{%8,%9},{%0,%1,%2,%3};"
        : "+f"(d[0]), "+f"(d[1]), "+f"(d[2]), "+f"(d[3])
        : "r"(a[0]), "r"(a[1]), "r"(a[2]), "r"(a[3]), "r"(b[0]), "r"(b[1]));
}
__device__ __forceinline__ void split8(const float* f, uint4& h, uint4& l) {
    unsigned hu[4], lu[4];
    #pragma unroll
    for (int i = 0; i < 4; i++) {
        float a = f[2*i], b = f[2*i+1];
        __nv_bfloat16 ha = __float2bfloat16(a), hb = __float2bfloat16(b);
        float ra = a - __bfloat162float(ha), rb = b - __bfloat162float(hb);
        __nv_bfloat16 la = __float2bfloat16(ra), lb = __float2bfloat16(rb);
        hu[i] = (unsigned)__bfloat16_as_ushort(ha) | ((unsigned)__bfloat16_as_ushort(hb) << 16);
        lu[i] = (unsigned)__bfloat16_as_ushort(la) | ((unsigned)__bfloat16_as_ushort(lb) << 16);
    }
    h = make_uint4(hu[0], hu[1], hu[2], hu[3]);
    l = make_uint4(lu[0], lu[1], lu[2], lu[3]);
}

// ---------------- K_wo: split Wo into bf16 hi/lo ---------------------------------
__global__ void k_split_wo(const float* __restrict__ Wo) {
    unsigned i4 = blockIdx.x*256u + threadIdx.x;   // 262144 float4 groups
    float4 v = ((const float4*)Wo)[i4];
    float f[4] = {v.x, v.y, v.z, v.w};
    unsigned hu[2], lu[2];
    #pragma unroll
    for (int i = 0; i < 2; i++) {
        float a = f[2*i], b = f[2*i+1];
        __nv_bfloat16 ha = __float2bfloat16(a), hb = __float2bfloat16(b);
        float ra = a - __bfloat162float(ha), rb = b - __bfloat162float(hb);
        __nv_bfloat16 la = __float2bfloat16(ra), lb = __float2bfloat16(rb);
        hu[i] = (unsigned)__bfloat16_as_ushort(ha) | ((unsigned)__bfloat16_as_ushort(hb) << 16);
        lu[i] = (unsigned)__bfloat16_as_ushort(la) | ((unsigned)__bfloat16_as_ushort(lb) << 16);
    }
    ((uint2*)g_woh)[i4] = make_uint2(hu[0], hu[1]);
    ((uint2*)g_wol)[i4] = make_uint2(lu[0], lu[1]);
}

// ---------------- K1: router — 4 tokens per block --------------------------------
__global__ void k_router(const float* __restrict__ x, const float* __restrict__ Wr) {
    __shared__ float xs[4][E_];
    __shared__ float part[4][8][H_];
    int s0 = blockIdx.x * 4, t = threadIdx.x;
    for (int i = t; i < 4*E_; i += 256) xs[i >> 10][i & 1023] = x[s0*E_ + i];
    __syncthreads();
    int c = t & 31, pr = t >> 5;
    float a0 = 0.f, a1 = 0.f, a2 = 0.f, a3 = 0.f;
    int e0 = pr * 128;
    #pragma unroll 4
    for (int e = e0; e < e0 + 128; e++) {
        float w = Wr[e*H_ + c];
        a0 += xs[0][e]*w; a1 += xs[1][e]*w; a2 += xs[2][e]*w; a3 += xs[3][e]*w;
    }
    part[0][pr][c] = a0; part[1][pr][c] = a1; part[2][pr][c] = a2; part[3][pr][c] = a3;
    __syncthreads();
    if (t < 128) {
        int tok = t >> 5, lane = t & 31;
        int s = s0 + tok;
        float l = 0.f;
        #pragma unroll
        for (int p = 0; p < 8; p++) l += part[tok][p][lane];
        float m = l;
        for (int o = 16; o; o >>= 1) m = fmaxf(m, __shfl_xor_sync(0xffffffffu, m, o));
        float ex = expf(l - m);
        float sum = ex;
        for (int o = 16; o; o >>= 1) sum += __shfl_xor_sync(0xffffffffu, sum, o);
        float p = ex / sum;
        g_probs[s*H_ + lane] = p;
        float et = p * logf(p + 1e-8f);
        float ent = et;
        for (int o = 16; o; o >>= 1) ent += __shfl_xor_sync(0xffffffffu, ent, o);
        if (lane == 0) {
            g_ent[s] = -ent;
            float lse = m + logf(sum);
            g_z[s] = lse * lse;
        }
        float lv = l;
        float topl[KSEL];
        int   topi[KSEL];
        for (int kk = 0; kk < KSEL; kk++) {
            float v = lv; int idx = lane;
            for (int o = 16; o; o >>= 1) {
                float ov = __shfl_xor_sync(0xffffffffu, v, o);
                int   oi = __shfl_xor_sync(0xffffffffu, idx, o);
                if (ov > v || (ov == v && oi < idx)) { v = ov; idx = oi; }
            }
            if (lane == 0) { topl[kk] = v; topi[kk] = idx; }
            if (lane == idx) lv = -INFINITY;
        }
        if (lane == 0) {
            for (int kk = 0; kk < KSEL; kk++) g_head_idx[s*KSEL + kk] = topi[kk];
            g_primary[s] = topi[0];
            float m2 = topl[0], sm2 = 0.f, w[KSEL];
            for (int kk = 0; kk < KSEL; kk++) { w[kk] = expf(topl[kk] - m2); sm2 += w[kk]; }
            float inv2 = 1.f / sm2;
            for (int kk = 0; kk < KSEL; kk++) g_head_w[s*KSEL + kk] = w[kk] * inv2;
        }
    }
}

// ---------------- K2: group-by-head build (deterministic, no atomics) ----------
__global__ void k_build(const int* __restrict__ head_counts) {
    __shared__ int ccnt[8][H_];
    int t = threadIdx.x;
    int h = t & 31, ch = t >> 5;
    int c0 = ch * 1024, c1 = c0 + 1024;
    int cnt = 0;
    for (int i = c0; i < c1; i++) cnt += (g_head_idx[i] == h);
    ccnt[ch][h] = cnt;
    __syncthreads();
    if (t < 32) {
        int tot = 0;
        #pragma unroll
        for (int c = 0; c < 8; c++) tot += ccnt[c][t];
        g_nh[t] = tot;
    }
    __syncthreads();
    if (t == 0) {
        int o = 0;
        for (int hh = 0; hh < H_; hh++) { g_off[hh] = o; o += g_nh[hh]; }
        g_off[H_] = o;
        int nt = 0;
        for (int hh = 0; hh < H_; hh++) {
            for (int st = 0; st < g_nh[hh]; st += 32) {
                g_tile_head[nt] = hh;
                g_tile_start[nt] = g_off[hh] + st;
                g_tile_m[nt] = min(32, g_nh[hh] - st);
                nt++;
            }
        }
        g_ntiles = nt;
        int nt64 = 0;
        for (int hh = 0; hh < H_; hh++) {
            for (int st = 0; st < g_nh[hh]; st += 64) {
                g_t64_head[nt64] = hh;
                g_t64_start[nt64] = g_off[hh] + st;
                g_t64_m[nt64] = min(64, g_nh[hh] - st);
                nt64++;
            }
        }
        g_ntiles64 = nt64;
    }
    __syncthreads();
    int base = g_off[h];
    for (int c = 0; c < ch; c++) base += ccnt[c][h];
    int hc = head_counts[h];
    int local = 0;
    for (int i = c0; i < c1; i++) {
        if (g_head_idx[i] == h) {
            int pp = base + local;
            g_perm[pp] = i;
            int rank = pp - g_off[h];
            int pos = rank + hc;
            pos = max(0, min(pos, MAXPOS));
            g_pos[pp] = pos;
            local++;
        }
    }
}

// ---------------- K2b: RoPE table (pow hoisted per thread) -----------------------
__global__ void k_ropetab() {
    int t = threadIdx.x;
    int i = t & 63;
    double ex  = (double)(2 * i) / 128.0;
    double invf = pow(10000.0, -ex);
    const double TWO_PI = 6.283185307179586476925286766559;
    int j0 = blockIdx.x * 64;
    for (int jj = t >> 6; jj < 64; jj += 4) {
        int j = j0 + jj;
        double ang = (double)g_pos[j] * invf;
        double r = ang - floor(ang / TWO_PI + 0.5) * TWO_PI;   // |r| <= pi
        float fr = (float)r;
        g_cos[j*64 + i] = cosf(fr);
        g_sin[j*64 + i] = sinf(fr);
    }
}

// ---------------- K3: grouped QKV GEMM (on-the-fly split) + RoPE + bf16 out ----
__global__ void k_qkv_mma(const float* __restrict__ x,
                          const float* __restrict__ Wq,
                          const float* __restrict__ Wk,
                          const float* __restrict__ Wv) {
    extern __shared__ unsigned char dsm[];
    __shared__ int srow[64];
    int tb = blockIdx.x;
    if (tb >= g_ntiles64) return;
    int w = blockIdx.y;
    int h     = g_t64_head[tb];
    int start = g_t64_start[tb];
    int m     = g_t64_m[tb];
    int t = threadIdx.x;
    if (t < 64) {
        int j = start + ((t < m) ? t : 0);
        srow[t] = g_perm[j] >> 3;
    }
    __syncthreads();

    int lane = t & 31, wid = t >> 5;
    int m0w = (wid & 1) * 32, n0w = (wid >> 1) * 32;
    float acc[2][4][4];
    #pragma unroll
    for (int mi = 0; mi < 2; mi++)
        #pragma unroll
        for (int nj = 0; nj < 4; nj++)
            #pragma unroll
            for (int q = 0; q < 4; q++) acc[mi][nj][q] = 0.f;

    const float* W = (w == 0) ? Wq : (w == 1) ? Wk : Wv;

    unsigned smbase = (unsigned)__cvta_generic_to_shared(dsm);
    unsigned aHiB = smbase, aLoB = smbase + 8192u, bHiB = smbase + 16384u, bLoB = smbase + 32768u;

    int rowA = t >> 3, cA = t & 7;
    int kB0 = t >> 4, cB = t & 15;

    for (int kc = 0; kc < E_; kc += 64) {
        __syncthreads();
        #pragma unroll
        for (int rr = 0; rr < 2; rr++) {
            int row = rowA + rr * 32;
            const float* xp = x + (size_t)srow[row]*E_ + kc + cA*8;
            float f[8];
            *(float4*)&f[0] = *(const float4*)xp;
            *(float4*)&f[4] = *(const float4*)(xp + 4);
            uint4 hi, lo;
            split8(f, hi, lo);
            int cp = cA ^ (row & 7);
            ((uint4*)dsm)[row*8 + cp] = hi;
            ((uint4*)(dsm + 8192))[row*8 + cp] = lo;
        }
        #pragma unroll
        for (int kk = 0; kk < 4; kk++) {
            int k = kB0 + kk * 16;
            const float* wp = W + (size_t)(kc + k)*(H_*D_) + h*D_ + cB*8;
            float f[8];
            *(float4*)&f[0] = *(const float4*)wp;
            *(float4*)&f[4] = *(const float4*)(wp + 4);
            uint4 vh, vl;
            split8(f, vh, vl);
            int cp = cB ^ (k & 15);
            ((uint4*)(dsm + 16384))[k*16 + cp] = vh;
            ((uint4*)(dsm + 32768))[k*16 + cp] = vl;
        }
        __syncthreads();

        #pragma unroll
        for (int s = 0; s < 4; s++) {
            unsigned ah[2][4], al[2][4];
            #pragma unroll
            for (int mi = 0; mi < 2; mi++) {
                int row = m0w + mi*16 + (lane & 7) + (lane & 8);
                int kch = 2*s + (lane >> 4);
                unsigned off = (unsigned)(row*8 + (kch ^ (row & 7))) * 16u;
                ldm4(ah[mi], aHiB + off);
                ldm4(al[mi], aLoB + off);
            }
            unsigned bh[2][4], bl[2][4];
            #pragma unroll
            for (int p = 0; p < 2; p++) {
                int k = s*16 + (lane & 7) + (lane & 8);
                int ncn = (n0w >> 3) + p*2 + (lane >> 4);
                unsigned off = (unsigned)(k*16 + (ncn ^ (k & 15))) * 16u;
                ldm4t(bh[p], bHiB + off);
                ldm4t(bl[p], bLoB + off);
            }
            #pragma unroll
            for (int mi = 0; mi < 2; mi++)
                #pragma unroll
                for (int nj = 0; nj < 4; nj++) {
                    const unsigned* Bh = &bh[nj >> 1][(nj & 1)*2];
                    const unsigned* Bl = &bl[nj >> 1][(nj & 1)*2];
                    mma16816(acc[mi][nj], ah[mi], Bh);
                    mma16816(acc[mi][nj], ah[mi], Bl);
                    mma16816(acc[mi][nj], al[mi], Bh);
                }
        }
    }

    __syncthreads();
    float* Sb = (float*)(dsm + 16384);
    int g = lane >> 2, tt = lane & 3;
    #pragma unroll
    for (int mi = 0; mi < 2; mi++)
        #pragma unroll
        for (int nj = 0; nj < 4; nj++) {
            int r0 = m0w + mi*16 + g;
            int c0 = n0w + nj*8 + 2*tt;
            Sb[r0*128 + c0]       = acc[mi][nj][0];
            Sb[r0*128 + c0 + 1]   = acc[mi][nj][1];
            Sb[(r0+8)*128 + c0]   = acc[mi][nj][2];
            Sb[(r0+8)*128 + c0+1] = acc[mi][nj][3];
        }
    __syncthreads();
    unsigned short* dsth = (w == 0) ? g_qh : (w == 1) ? g_kh : g_vh;
    unsigned short* dstl = (w == 0) ? g_ql : (w == 1) ? g_kl : g_vl;
    for (int idx = t; idx < 64*128; idx += 256) {
        int r = idx >> 7, c = idx & 127;
        if (r < m) {
            int j = start + r;
            float val = Sb[r*128 + c];
            float outv;
            if (w < 2) {
                int ih = c & 63;
                float cs = g_cos[j*64 + ih], sn = g_sin[j*64 + ih];
                outv = (c < 64) ? val*cs - Sb[r*128 + c + 64]*sn
                                : val*cs + Sb[r*128 + c - 64]*sn;
            } else outv = val;
            __nv_bfloat16 hb = __float2bfloat16(outv);
            float rem = outv - __bfloat162float(hb);
            dsth[(size_t)j*D_ + c] = __bfloat16_as_ushort(hb);
            dstl[(size_t)j*D_ + c] = __bfloat16_as_ushort(__float2bfloat16(rem));
        }
    }
}

// ---------------- K4: tensor-core flash attention (split-bf16) ------------------
// block = one 32-query tile of a head; key chunks of 64; online softmax.
__global__ void k_attn3() {
    extern __shared__ unsigned char sm8[];
    // byte offsets
    unsigned short* Ph = (unsigned short*)(sm8 + 90368);   // [32][64] bf16
    unsigned short* Pl = (unsigned short*)(sm8 + 94464);
    float* S = (float*)(sm8 + 81920);                      // [32][66] f32
    __shared__ float s_m[32], s_l[32], s_scale[32];

    unsigned smb = (unsigned)__cvta_generic_to_shared(sm8);
    unsigned qhB = smb, qlB = smb + 8192u;
    unsigned khB = smb + 16384u, klB = smb + 32768u;
    unsigned vhB = smb + 49152u, vlB = smb + 65536u;
    unsigned phB = smb + 90368u, plB = smb + 94464u;

    int tb = blockIdx.x;
    if (tb >= g_ntiles) return;
    int h = g_tile_head[tb], start = g_tile_start[tb], m = g_tile_m[tb];
    int off = g_off[h];
    int t = threadIdx.x;
    int lane = t & 31, wid = t >> 5;

    // stage Q (once): [32][128] bf16 hi/lo, swizzled c^(r&15)
    for (int idx = t; idx < 512; idx += 256) {
        int r = idx >> 4, c = idx & 15;
        int j = start + ((r < m) ? r : (m - 1));
        int cp = c ^ (r & 15);
        ((uint4*)sm8)[r*16 + cp]             = *(const uint4*)&g_qh[(size_t)j*D_ + c*8];
        ((uint4*)(sm8 + 8192))[r*16 + cp]    = *(const uint4*)&g_ql[(size_t)j*D_ + c*8];
    }
    if (t < 32) { s_m[t] = -1e30f; s_l[t] = 0.f; s_scale[t] = 0.f; }

    // O accumulators: warp tile 32(m) x 16(n) at n0 = wid*16
    float facc[2][2][4];
    #pragma unroll
    for (int a = 0; a < 2; a++)
        #pragma unroll
        for (int b = 0; b < 2; b++)
            #pragma unroll
            for (int q = 0; q < 4; q++) facc[a][b][q] = 0.f;

    int g = lane >> 2, tt = lane & 3;
    int kend = start + m;

    for (int koff = off; koff < kend; koff += 64) {
        int kn = min(64, kend - koff);
        __syncthreads();
        // stage K/V chunk: [64][128] bf16 hi/lo x4 arrays
        for (int idx = t; idx < 1024; idx += 256) {
            int r = idx >> 4, c = idx & 15;
            int kj = koff + ((r < kn) ? r : (kn - 1));
            int cp = c ^ (r & 15);
            size_t gidx = (size_t)kj*D_ + c*8;
            ((uint4*)(sm8 + 16384))[r*16 + cp] = *(const uint4*)&g_kh[gidx];
            ((uint4*)(sm8 + 32768))[r*16 + cp] = *(const uint4*)&g_kl[gidx];
            ((uint4*)(sm8 + 49152))[r*16 + cp] = *(const uint4*)&g_vh[gidx];
            ((uint4*)(sm8 + 65536))[r*16 + cp] = *(const uint4*)&g_vl[gidx];
        }
        __syncthreads();

        // scores: warp computes S[32 q][8 k] at n0s = wid*8
        float accs[2][4];
        #pragma unroll
        for (int mf = 0; mf < 2; mf++)
            #pragma unroll
            for (int q = 0; q < 4; q++) accs[mf][q] = 0.f;
        int n0s = wid * 8;
        #pragma unroll
        for (int ks = 0; ks < 8; ks++) {
            unsigned ah[2][4], al[2][4];
            #pragma unroll
            for (int mf = 0; mf < 2; mf++) {
                int row = mf*16 + (lane & 7) + (lane & 8);
                int kch = 2*ks + (lane >> 4);
                unsigned o2 = (unsigned)(row*16 + (kch ^ (row & 15))) * 16u;
                ldm4(ah[mf], qhB + o2);
                ldm4(al[mf], qlB + o2);
            }
            // B = K rows [n][k], non-trans x2: lanes 0-7 -> k-chunk 2ks, 8-15 -> 2ks+1
            unsigned bh[2], bl[2];
            {
                int l15 = lane & 15;
                int r = n0s + (l15 & 7);
                int c = 2*ks + (l15 >> 3);
                unsigned o2 = (unsigned)(r*16 + (c ^ (r & 15))) * 16u;
                ldm2(bh, khB + o2);
                ldm2(bl, klB + o2);
            }
            #pragma unroll
            for (int mf = 0; mf < 2; mf++) {
                mma16816(accs[mf], ah[mf], bh);
                mma16816(accs[mf], ah[mf], bl);
                mma16816(accs[mf], al[mf], bh);
            }
        }
        // write S fragments
        #pragma unroll
        for (int mf = 0; mf < 2; mf++) {
            int r0 = mf*16 + g;
            int c0 = n0s + 2*tt;
            S[r0*66 + c0]     = accs[mf][0];
            S[r0*66 + c0 + 1] = accs[mf][1];
            S[(r0+8)*66 + c0]     = accs[mf][2];
            S[(r0+8)*66 + c0 + 1] = accs[mf][3];
        }
        __syncthreads();

        // online softmax: thread -> (row r = t>>3, 8 cols at (t&7)*8)
        {
            int r = t >> 3;
            int jq = start + ((r < m) ? r : (m - 1));
            float mo = s_m[r];
            float pv[8];
            float mx = mo;
            int cbase = (t & 7) * 8;
            #pragma unroll
            for (int c = 0; c < 8; c++) {
                int col = cbase + c;
                int kg = koff + col;
                float sv = (col < kn && kg <= jq) ? S[r*66 + col] * SCALE_ : -1e30f;
                pv[c] = sv;
                mx = fmaxf(mx, sv);
            }
            #pragma unroll
            for (int o = 4; o; o >>= 1) mx = fmaxf(mx, __shfl_xor_sync(0xffffffffu, mx, o));
            float sum = 0.f;
            #pragma unroll
            for (int c = 0; c < 8; c++) {
                float e = expf(pv[c] - mx);
                pv[c] = e;
                sum += e;
            }
            #pragma unroll
            for (int o = 4; o; o >>= 1) sum += __shfl_xor_sync(0xffffffffu, sum, o);
            uint4 hi, lo;
            split8(pv, hi, lo);
            int c4 = t & 7;
            int cp = c4 ^ (r & 7);
            ((uint4*)Ph)[r*8 + cp] = hi;
            ((uint4*)Pl)[r*8 + cp] = lo;
            if ((t & 7) == 0) {
                float sc = expf(mo - mx);
                s_scale[r] = sc;
                s_l[r] = s_l[r] * sc + sum;
                s_m[r] = mx;
            }
        }
        __syncthreads();

        // PV: rescale acc, then O += P @ V  (warp n-tile 16 at wid*16)
        {
            float sc[2][2];
            #pragma unroll
            for (int mf = 0; mf < 2; mf++) {
                sc[mf][0] = s_scale[mf*16 + g];
                sc[mf][1] = s_scale[mf*16 + g + 8];
            }
            #pragma unroll
            for (int mf = 0; mf < 2; mf++)
                #pragma unroll
                for (int nf = 0; nf < 2; nf++) {
                    facc[mf][nf][0] *= sc[mf][0];
                    facc[mf][nf][1] *= sc[mf][0];
                    facc[mf][nf][2] *= sc[mf][1];
                    facc[mf][nf][3] *= sc[mf][1];
                }
            #pragma unroll
            for (int ks = 0; ks < 4; ks++) {
                unsigned pah[2][4], pal[2][4];
                #pragma unroll
                for (int mf = 0; mf < 2; mf++) {
                    int row = mf*16 + (lane & 7) + (lane & 8);
                    int kch = 2*ks + (lane >> 4);
                    unsigned o2 = (unsigned)(row*8 + (kch ^ (row & 7))) * 16u;
                    ldm4(pah[mf], phB + o2);
                    ldm4(pal[mf], plB + o2);
                }
                unsigned vbh[4], vbl[4];
                {
                    int kk = ks*16 + (lane & 7) + (lane & 8);
                    int ncn = wid*2 + (lane >> 4);
                    unsigned o2 = (unsigned)(kk*16 + (ncn ^ (kk & 15))) * 16u;
                    ldm4t(vbh, vhB + o2);
                    ldm4t(vbl, vlB + o2);
                }
                #pragma unroll
                for (int mf = 0; mf < 2; mf++)
                    #pragma unroll
                    for (int nf = 0; nf < 2; nf++) {
                        mma16816(facc[mf][nf], pah[mf], &vbh[nf*2]);
                        mma16816(facc[mf][nf], pah[mf], &vbl[nf*2]);
                        mma16816(facc[mf][nf], pal[mf], &vbh[nf*2]);
                    }
            }
        }
    }

    // write output rows (scaled by head weight / l)
    #pragma unroll
    for (int mf = 0; mf < 2; mf++) {
        int r1 = mf*16 + g;
        int r2 = r1 + 8;
        #pragma unroll
        for (int nf = 0; nf < 2; nf++) {
            int c = wid*16 + nf*8 + 2*tt;
            if (r1 < m) {
                int e = g_perm[start + r1];
                float ws = g_head_w[e] / s_l[r1];
                *(float2*)&g_mid[(size_t)e*D_ + c] =
                    make_float2(facc[mf][nf][0]*ws, facc[mf][nf][1]*ws);
            }
            if (r2 < m) {
                int e = g_perm[start + r2];
                float ws = g_head_w[e] / s_l[r2];
                *(float2*)&g_mid[(size_t)e*D_ + c] =
                    make_float2(facc[mf][nf][2]*ws, facc[mf][nf][3]*ws);
            }
        }
    }
}

// ---------------- K5: output projection (bf16-split tensor core) ---------------
__global__ void k_out_mma(float* __restrict__ out) {
    extern __shared__ unsigned char dsm[];
    int n0 = blockIdx.x * 128;
    int m0 = blockIdx.y * 64;
    int t = threadIdx.x;
    int lane = t & 31, wid = t >> 5;
    int m0w = (wid & 1) * 32, n0w = (wid >> 1) * 32;
    float acc[2][4][4];
    #pragma unroll
    for (int mi = 0; mi < 2; mi++)
        #pragma unroll
        for (int nj = 0; nj < 4; nj++)
            #pragma unroll
            for (int q = 0; q < 4; q++) acc[mi][nj][q] = 0.f;

    unsigned smbase = (unsigned)__cvta_generic_to_shared(dsm);
    unsigned aHiB = smbase, aLoB = smbase + 8192u, bHiB = smbase + 16384u, bLoB = smbase + 32768u;

    int rowA = t >> 3, cA = t & 7;
    int kB0 = t >> 4, cB = t & 15;

    for (int kc = 0; kc < 1024; kc += 64) {
        __syncthreads();
        #pragma unroll
        for (int rr = 0; rr < 2; rr++) {
            int row = rowA + rr * 32;
            const float* xp = g_mid + (size_t)(m0 + row)*1024 + kc + cA*8;
            float f[8];
            *(float4*)&f[0] = *(const float4*)xp;
            *(float4*)&f[4] = *(const float4*)(xp + 4);
            uint4 hi, lo;
            split8(f, hi, lo);
            int cp = cA ^ (row & 7);
            ((uint4*)dsm)[row*8 + cp] = hi;
            ((uint4*)(dsm + 8192))[row*8 + cp] = lo;
        }
        #pragma unroll
        for (int kk = 0; kk < 4; kk++) {
            int k = kB0 + kk * 16;
            size_t gi = (size_t)(kc + k)*1024u + n0 + cB*8u;
            uint4 vh = *(const uint4*)(g_woh + gi);
            uint4 vl = *(const uint4*)(g_wol + gi);
            int cp = cB ^ (k & 15);
            ((uint4*)(dsm + 16384))[k*16 + cp] = vh;
            ((uint4*)(dsm + 32768))[k*16 + cp] = vl;
        }
        __syncthreads();

        #pragma unroll
        for (int s = 0; s < 4; s++) {
            unsigned ah[2][4], al[2][4];
            #pragma unroll
            for (int mi = 0; mi < 2; mi++) {
                int row = m0w + mi*16 + (lane & 7) + (lane & 8);
                int kch = 2*s + (lane >> 4);
                unsigned off = (unsigned)(row*8 + (kch ^ (row & 7))) * 16u;
                ldm4(ah[mi], aHiB + off);
                ldm4(al[mi], aLoB + off);
            }
            unsigned bh[2][4], bl[2][4];
            #pragma unroll
            for (int p = 0; p < 2; p++) {
                int k = s*16 + (lane & 7) + (lane & 8);
                int ncn = (n0w >> 3) + p*2 + (lane >> 4);
                unsigned off = (unsigned)(k*16 + (ncn ^ (k & 15))) * 16u;
                ldm4t(bh[p], bHiB + off);
                ldm4t(bl[p], bLoB + off);
            }
            #pragma unroll
            for (int mi = 0; mi < 2; mi++)
                #pragma unroll
                for (int nj = 0; nj < 4; nj++) {
                    const unsigned* Bh = &bh[nj >> 1][(nj & 1)*2];
                    const unsigned* Bl = &bl[nj >> 1][(nj & 1)*2];
                    mma16816(acc[mi][nj], ah[mi], Bh);
                    mma16816(acc[mi][nj], ah[mi], Bl);
                    mma16816(acc[mi][nj], al[mi], Bh);
                }
        }
    }

    int g = lane >> 2, tt = lane & 3;
    #pragma unroll
    for (int mi = 0; mi < 2; mi++)
        #pragma unroll
        for (int nj = 0; nj < 4; nj++) {
            int r = m0 + m0w + mi*16 + g;
            int c = n0 + n0w + nj*8 + 2*tt;
            *(float2*)&out[(size_t)r*1024 + c]     = make_float2(acc[mi][nj][0], acc[mi][nj][1]);
            *(float2*)&out[(size_t)(r+8)*1024 + c] = make_float2(acc[mi][nj][2], acc[mi][nj][3]);
        }
}

// ---------------- K6: counts + aux loss (deterministic reductions) --------------
__global__ void k_final(const int* __restrict__ head_counts, float* __restrict__ out, int out_size) {
    __shared__ float fb[H_];
    int t = threadIdx.x;   // 32 threads
    float psum = 0.f; int fcnt = 0;
    for (int s = 0; s < S_; s++) {
        psum += g_probs[s*H_ + t];
        fcnt += (g_primary[s] == t);
    }
    float f = (float)fcnt / (float)S_;
    float p = psum / (float)S_;
    fb[t] = f * p;
    if (out_size >= S_*E_ + H_)
        out[S_*E_ + t] = (float)(g_nh[t] + head_counts[t]);
    float es = 0.f, zs = 0.f;
    for (int s = t; s < S_; s += 32) { es += g_ent[s]; zs += g_z[s]; }
    for (int o = 16; o; o >>= 1) {
        es += __shfl_xor_sync(0xffffffffu, es, o);
        zs += __shfl_xor_sync(0xffffffffu, zs, o);
    }
    __syncwarp();
    if (t == 0) {
        float bal = 0.f;
        for (int hh = 0; hh < H_; hh++) bal += fb[hh];
        bal *= (float)H_;
        float ent_loss = -es / (float)S_;
        float z_loss   = (zs / (float)S_) * 0.01f;
        float aux = 0.01f * bal + 0.01f * ent_loss + z_loss;
        if (out_size >= S_*E_ + H_ + 1) out[S_*E_ + H_] = aux;
    }
}

// ---------------- launch ---------------------------------------------------------
extern "C" void kernel_launch(void* const* d_in, const int* in_sizes, int n_in,
                              void* d_out, int out_size) {
    const float* x  = (const float*)d_in[0];
    const float* Wq = (const float*)d_in[1];
    const float* Wk = (const float*)d_in[2];
    const float* Wv = (const float*)d_in[3];
    const float* Wr = (const float*)d_in[4];
    const float* Wo = (const float*)d_in[5];
    const int*   hc = (const int*)d_in[6];
    float* out = (float*)d_out;

    const int attn_smem = 98560;

    cudaFuncSetAttribute(k_qkv_mma, cudaFuncAttributeMaxDynamicSharedMemorySize, 49152);
    cudaFuncSetAttribute(k_out_mma, cudaFuncAttributeMaxDynamicSharedMemorySize, 49152);
    cudaFuncSetAttribute(k_attn3,  cudaFuncAttributeMaxDynamicSharedMemorySize, attn_smem);

    k_router<<<256, 256>>>(x, Wr);                 // 1
    k_build<<<1, 256>>>(hc);                       // 2
    k_ropetab<<<128, 256>>>();                     // 3
    k_qkv_mma<<<dim3(160, 3), 256, 49152>>>(x, Wq, Wk, Wv);   // 4 <- profiled
    k_attn3<<<300, 256, attn_smem>>>();            // 5
    k_split_wo<<<1024, 256>>>(Wo);                 // 6
    k_out_mma<<<dim3(8, 16), 256, 49152>>>(out);   // 7
    k_final<<<1, 32>>>(hc, out, out_size);         // 8
}